// round 14
// baseline (speedup 1.0000x reference)
#include <cuda_runtime.h>
#include <cstdint>
#include <cuda_fp16.h>

#define NB 128
#define NS 256
#define NH 1024
#define NE 512
#define NV 32000
#define NL 2

#define OFF_PRED 0
#define OFF_HID  (NB*NV)
#define OFF_CELL (OFF_HID + NL*NB*NH)
#define OFF_ATTN (OFF_CELL + NL*NB*NH)

#define EPI_STORE 0
#define EPI_ATTN  2

// -------- device scratch --------
__device__ __align__(16) __half g_ench[NB*NS*NH];    // fp16 encoder (67MB)
__device__ __align__(16) __half g_w1h[NH*NH];        // fp16 W1
__device__ __align__(16) __half g_fcwh[(size_t)NV*2*NH]; // fp16 fc_w (131MB)
__device__ __align__(16) __half g_cat2h[NB*2*NH];    // fp16 [h1_new, ctx]
__device__ __align__(16) float g_q[NB*NH];
__device__ __align__(16) float g_qpart[8*NB*NH];
__device__ __align__(16) float g_spart[4*NB*NS];
__device__ __align__(16) float g_context[NB*NH];
__device__ __align__(16) float g_x0[NB*(NE+2*NH)];   // [emb, ctx, h0_prev]
__device__ __align__(16) float g_x1[NB*2*NH];        // [h0_new, h1_prev]
__device__ __align__(16) float g_gpart[8*NB*4*NH];
__device__ __align__(16) float g_fcpart[2*NB*NV];

__device__ __forceinline__ uint32_t smem_u32(const void* p){
  uint32_t a; asm("{ .reg .u64 t; cvta.to.shared.u64 t, %1; cvt.u32.u64 %0, t; }" : "=r"(a) : "l"(p));
  return a;
}
__device__ __forceinline__ uint32_t packh2(float2 v){
  uint32_t r; asm("cvt.rn.f16x2.f32 %0, %1, %2;" : "=r"(r) : "f"(v.y), "f"(v.x)); return r;
}
__device__ __forceinline__ void mma16(float* d, const uint32_t* a, const uint32_t* b){
  asm volatile("mma.sync.aligned.m16n8k16.row.col.f32.f16.f16.f32 "
    "{%0,%1,%2,%3},{%4,%5,%6,%7},{%8,%9},{%0,%1,%2,%3};"
    : "+f"(d[0]),"+f"(d[1]),"+f"(d[2]),"+f"(d[3])
    : "r"(a[0]),"r"(a[1]),"r"(a[2]),"r"(a[3]),"r"(b[0]),"r"(b[1]));
}
__device__ __forceinline__ void ldsm4(uint32_t& r0,uint32_t& r1,uint32_t& r2,uint32_t& r3, uint32_t addr){
  asm volatile("ldmatrix.sync.aligned.m8n8.x4.shared.b16 {%0,%1,%2,%3}, [%4];"
    : "=r"(r0),"=r"(r1),"=r"(r2),"=r"(r3) : "r"(addr));
}

// ============ fp16-NATIVE GEMM: C(M,N)=A(M,K)@B(N,K)^T ============
// 256 threads / 8 warps. cp.async direct, BK=32, 3 stages.
// Split-K via blockIdx.z: kOff=z*kLen, C offset z*M*N (bias null then).
template<int BN, int EPI>
__global__ void __launch_bounds__(256,1) gemm16h(
    const __half* __restrict__ A, const __half* __restrict__ B,
    float* __restrict__ C, int M, int N, int K, int kLen,
    const float* __restrict__ bias,
    const float* __restrict__ qv, const float* __restrict__ vw, float* __restrict__ spart)
{
  constexpr int BM = 128, BK = 32, NSTG = 3;
  constexpr int WN = BN/4, NF = WN/8, NPB = NF/2;
  constexpr int RSB = 80;
  constexpr int STAGE = (BM+BN)*RSB;
  constexpr int CPT = (BM+BN)*4/256;

  extern __shared__ char dsm[];
  __shared__ float sBias[BN], sQ[BN], sVw[BN];
  __shared__ float srow[BM];

  const uint32_t smb = smem_u32(dsm);
  const int tid = threadIdx.x, warp = tid>>5, lane = tid&31;
  const int g = lane>>2, tq = lane&3;
  const int wm = (warp&1)*64, wn = (warp>>1)*WN;
  const size_t m0 = (size_t)blockIdx.y*BM;
  const int n0 = blockIdx.x*BN;
  const int kOff = blockIdx.z*kLen;
  const int kt = kLen/BK;

  if (tid < BN){
    sBias[tid] = bias ? bias[n0+tid] : 0.f;
    if (EPI == EPI_ATTN){ sVw[tid] = vw[n0+tid]; sQ[tid] = qv[(m0/NS)*NH + n0 + tid]; }
  }
  if (EPI == EPI_ATTN && tid < BM) srow[tid] = 0.f;

  uint32_t offA[4], offB[NPB];
  {
    int rA = (lane & 15), kcA = (lane >> 4) * 16;
    #pragma unroll
    for (int mt = 0; mt < 4; mt++) offA[mt] = (uint32_t)((wm + mt*16 + rA)*RSB + kcA);
    int rB = (lane & 7) + ((lane >= 16) ? 8 : 0), kcB = ((lane >> 3) & 1) * 16;
    #pragma unroll
    for (int np = 0; np < NPB; np++) offB[np] = (uint32_t)((BM + wn + np*16 + rB)*RSB + kcB);
  }

  float acc[4][NF][4];
  #pragma unroll
  for (int i=0;i<4;i++)
    #pragma unroll
    for (int j=0;j<NF;j++)
      #pragma unroll
      for (int k=0;k<4;k++) acc[i][j][k]=0.f;

  auto fill = [&](int s, int t){
    const uint32_t base = smb + (uint32_t)s*STAGE;
    const int k0 = kOff + t*BK;
    #pragma unroll
    for (int i = 0; i < CPT; i++){
      int c = tid + i*256;
      int row = c>>2, q = c&3;
      const __half* src = (row < BM)
        ? A + (m0 + row)*(size_t)K + k0 + q*8
        : B + (size_t)(n0 + row - BM)*K + k0 + q*8;
      uint32_t dst = base + (uint32_t)(row*RSB + q*16);
      asm volatile("cp.async.cg.shared.global [%0], [%1], 16;" :: "r"(dst), "l"(src) : "memory");
    }
    asm volatile("cp.async.commit_group;" ::: "memory");
  };

  fill(0,0); fill(1,1);

  for (int j = 0; j < kt; j++){
    asm volatile("cp.async.wait_group 1;" ::: "memory");
    __syncthreads();
    if (j+2 < kt) fill((j+2)%NSTG, j+2);
    else asm volatile("cp.async.commit_group;" ::: "memory");

    const uint32_t sb = smb + (uint32_t)(j%NSTG)*STAGE;
    #pragma unroll
    for (int ks = 0; ks < 2; ks++){
      uint32_t af[4][4], bf[NF][2];
      #pragma unroll
      for (int mt = 0; mt < 4; mt++)
        ldsm4(af[mt][0], af[mt][1], af[mt][2], af[mt][3], sb + offA[mt] + ks*32);
      #pragma unroll
      for (int np = 0; np < NPB; np++)
        ldsm4(bf[2*np][0], bf[2*np][1], bf[2*np+1][0], bf[2*np+1][1], sb + offB[np] + ks*32);
      #pragma unroll
      for (int mt = 0; mt < 4; mt++)
        #pragma unroll
        for (int nt = 0; nt < NF; nt++)
          mma16(acc[mt][nt], af[mt], bf[nt]);
    }
  }

  if (EPI == EPI_ATTN){
    __syncthreads();
    #pragma unroll
    for (int mt = 0; mt < 4; mt++){
      float p0 = 0.f, p1 = 0.f;
      #pragma unroll
      for (int nt = 0; nt < NF; nt++){
        int c = wn + nt*8 + 2*tq;
        float b0 = sBias[c]   + sQ[c];
        float b1 = sBias[c+1] + sQ[c+1];
        float v0 = sVw[c], v1 = sVw[c+1];
        p0 += tanhf(acc[mt][nt][0]+b0)*v0 + tanhf(acc[mt][nt][1]+b1)*v1;
        p1 += tanhf(acc[mt][nt][2]+b0)*v0 + tanhf(acc[mt][nt][3]+b1)*v1;
      }
      p0 += __shfl_xor_sync(0xffffffffu, p0, 1);
      p0 += __shfl_xor_sync(0xffffffffu, p0, 2);
      p1 += __shfl_xor_sync(0xffffffffu, p1, 1);
      p1 += __shfl_xor_sync(0xffffffffu, p1, 2);
      if (tq == 0){
        atomicAdd(&srow[wm+mt*16+g  ], p0);
        atomicAdd(&srow[wm+mt*16+g+8], p1);
      }
    }
    __syncthreads();
    if (tid < BM) spart[(size_t)blockIdx.x*M + m0 + tid] = srow[tid];
  } else {
    float* Cz = C + (size_t)blockIdx.z*M*N;
    #pragma unroll
    for (int mt = 0; mt < 4; mt++){
      #pragma unroll
      for (int nt = 0; nt < NF; nt++){
        size_t r = m0 + wm + mt*16 + g;
        int c = n0 + wn + nt*8 + 2*tq;
        float b0 = sBias[c - n0], b1 = sBias[c - n0 + 1];
        float2* p0 = (float2*)(Cz + r*N + c);
        float2* p1 = (float2*)(Cz + (r+8)*N + c);
        *p0 = make_float2(acc[mt][nt][0]+b0, acc[mt][nt][1]+b1);
        *p1 = make_float2(acc[mt][nt][2]+b0, acc[mt][nt][3]+b1);
      }
    }
  }
}

// ============ fp32-input GEMM (inline cvt, proven R7 ordering) ============
template<int BN, int EPI>
__global__ void __launch_bounds__(256,1) gemm16(
    const float* __restrict__ A, const float* __restrict__ B1, const float* __restrict__ B2,
    int Ksplit, float* __restrict__ C, int M, int N, int K, int kLen,
    const float* __restrict__ bias,
    const float* __restrict__ qv, const float* __restrict__ vw, float* __restrict__ spart)
{
  constexpr int BM = 128, BK = 16;
  constexpr int WN = BN/4, NF = WN/8, NPB = NF/2;
  constexpr int RSB = 48;
  constexpr int STAGE = (BM+BN)*RSB;
  constexpr int NLD = (BM+BN)*4/256;

  extern __shared__ char dsm[];
  __shared__ float sBias[BN];
  const uint32_t smb = smem_u32(dsm);
  const int tid = threadIdx.x, warp = tid>>5, lane = tid&31;
  const int g = lane>>2, tq = lane&3;
  const int wm = (warp&1)*64, wn = (warp>>1)*WN;
  const size_t m0 = (size_t)blockIdx.y*BM;
  const int n0 = blockIdx.x*BN;
  const int kOff = blockIdx.z*kLen;
  const int kt = kLen/BK;
  const int K2 = K - Ksplit;

  if (tid < BN) sBias[tid] = bias ? bias[n0+tid] : 0.f;

  uint32_t offA[4], offB[NPB];
  {
    int rA = (lane & 15), kcA = (lane >> 4) * 16;
    #pragma unroll
    for (int mt = 0; mt < 4; mt++) offA[mt] = (uint32_t)((wm + mt*16 + rA)*RSB + kcA);
    int rB = (lane & 7) + ((lane >= 16) ? 8 : 0), kcB = ((lane >> 3) & 1) * 16;
    #pragma unroll
    for (int np = 0; np < NPB; np++) offB[np] = (uint32_t)((BM + wn + np*16 + rB)*RSB + kcB);
  }

  float acc[4][NF][4];
  #pragma unroll
  for (int i=0;i<4;i++)
    #pragma unroll
    for (int j=0;j<NF;j++)
      #pragma unroll
      for (int k=0;k<4;k++) acc[i][j][k]=0.f;

  float4 v[NLD];
  int rown[NLD], quad[NLD];
  #pragma unroll
  for (int i = 0; i < NLD; i++){ int c = tid + i*256; rown[i] = c>>2; quad[i] = c&3; }

  auto ldg = [&](int t){
    const int k0 = kOff + t*BK;
    #pragma unroll
    for (int i = 0; i < NLD; i++){
      int kg = k0 + quad[i]*4;
      const float* src;
      if (rown[i] < BM) src = A + (m0 + rown[i])*(size_t)K + kg;
      else {
        int n = n0 + rown[i] - BM;
        if (kg < Ksplit) src = B1 + (size_t)n*Ksplit + kg;
        else             src = B2 + (size_t)n*K2 + (kg - Ksplit);
      }
      v[i] = *(const float4*)src;
    }
  };
  auto sts = [&](int s){
    const uint32_t base = smb + (uint32_t)s*STAGE;
    #pragma unroll
    for (int i = 0; i < NLD; i++){
      uint32_t lo = packh2(make_float2(v[i].x, v[i].y));
      uint32_t hi = packh2(make_float2(v[i].z, v[i].w));
      uint32_t dst = base + (uint32_t)(rown[i]*RSB + quad[i]*8);
      asm volatile("st.shared.v2.u32 [%0], {%1,%2};" :: "r"(dst), "r"(lo), "r"(hi) : "memory");
    }
  };

  ldg(0); sts(0);
  if (kt > 1) ldg(1);
  __syncthreads();

  for (int j = 0; j < kt; j++){
    const uint32_t sb = smb + (uint32_t)(j&1)*STAGE;
    uint32_t af[4][4], bf[NF][2];
    #pragma unroll
    for (int mt = 0; mt < 4; mt++)
      ldsm4(af[mt][0], af[mt][1], af[mt][2], af[mt][3], sb + offA[mt]);
    #pragma unroll
    for (int np = 0; np < NPB; np++)
      ldsm4(bf[2*np][0], bf[2*np][1], bf[2*np+1][0], bf[2*np+1][1], sb + offB[np]);
    #pragma unroll
    for (int mt = 0; mt < 4; mt++)
      #pragma unroll
      for (int nt = 0; nt < NF; nt++)
        mma16(acc[mt][nt], af[mt], bf[nt]);
    if (j+1 < kt){
      sts((j+1)&1);
      if (j+2 < kt) ldg(j+2);
    }
    __syncthreads();
  }

  float* Cz = C + (size_t)blockIdx.z*M*N;
  #pragma unroll
  for (int mt = 0; mt < 4; mt++){
    #pragma unroll
    for (int nt = 0; nt < NF; nt++){
      size_t r = m0 + wm + mt*16 + g;
      int c = n0 + wn + nt*8 + 2*tq;
      float b0 = sBias[c - n0], b1 = sBias[c - n0 + 1];
      float2* p0 = (float2*)(Cz + r*N + c);
      float2* p1 = (float2*)(Cz + (r+8)*N + c);
      *p0 = make_float2(acc[mt][nt][0]+b0, acc[mt][nt][1]+b1);
      *p1 = make_float2(acc[mt][nt][2]+b0, acc[mt][nt][3]+b1);
    }
  }
}

// ================= small kernels =================
__global__ void conv_k(const float4* __restrict__ src, uint2* __restrict__ dst, int n4){
  int i = blockIdx.x*256 + threadIdx.x;
  if (i >= n4) return;
  float4 v = src[i];
  uint2 o;
  o.x = packh2(make_float2(v.x, v.y));
  o.y = packh2(make_float2(v.z, v.w));
  dst[i] = o;
}

// grid-stride variant for the big fcw conversion (fewer blocks, co-resident friendly)
__global__ void conv_gs_k(const float4* __restrict__ src, uint2* __restrict__ dst, int n4){
  for (int i = blockIdx.x*256 + threadIdx.x; i < n4; i += gridDim.x*256){
    float4 v = src[i];
    uint2 o;
    o.x = packh2(make_float2(v.x, v.y));
    o.y = packh2(make_float2(v.z, v.w));
    dst[i] = o;
  }
}

__global__ void reduce_q_k(const float* __restrict__ qp, const float* __restrict__ w2b,
                           float* __restrict__ q){
  int i = blockIdx.x*256 + threadIdx.x;
  float s = w2b[i & (NH-1)];
  #pragma unroll
  for (int p = 0; p < 8; p++) s += qp[(size_t)p*NB*NH + i];
  q[i] = s;
}

__global__ void __launch_bounds__(NS) softmax_fused_k(const float* __restrict__ spart,
                                                      const float* __restrict__ vb,
                                                      float* __restrict__ attn_out){
  __shared__ float red[8];
  const int b = blockIdx.x, tid = threadIdx.x;
  const int m = b*NS + tid;
  float v = vb[0];
  #pragma unroll
  for (int j = 0; j < 4; j++) v += spart[(size_t)j*(NB*NS) + m];

  float mx = v;
  #pragma unroll
  for (int o = 16; o > 0; o >>= 1) mx = fmaxf(mx, __shfl_xor_sync(0xffffffffu, mx, o));
  if ((tid&31)==0) red[tid>>5] = mx;
  __syncthreads();
  if (tid == 0){ float x = red[0]; for (int i=1;i<8;i++) x = fmaxf(x, red[i]); red[0] = x; }
  __syncthreads();
  const float bm = red[0];
  __syncthreads();
  float e = expf(v - bm), s = e;
  #pragma unroll
  for (int o = 16; o > 0; o >>= 1) s += __shfl_xor_sync(0xffffffffu, s, o);
  if ((tid&31)==0) red[tid>>5] = s;
  __syncthreads();
  if (tid == 0){ float x = 0.f; for (int i=0;i<8;i++) x += red[i]; red[0] = x; }
  __syncthreads();
  attn_out[m] = e / red[0];
}

// context from fp16 enc; writes fp32 ctx + x0 slot, fp16 cat2h slot
__global__ void __launch_bounds__(128) ctx_k(const float* __restrict__ attn,
                                             const __half* __restrict__ ench,
                                             float* __restrict__ ctx,
                                             float* __restrict__ x0,
                                             __half* __restrict__ cat2h){
  __shared__ float sa[NS];
  const int b = blockIdx.x, hc = blockIdx.y, tid = threadIdx.x;
  sa[tid]     = attn[b*NS + tid];
  sa[tid+128] = attn[b*NS + tid + 128];
  __syncthreads();
  const int h4 = hc*512 + tid*4;
  const __half* ep = ench + (size_t)b*NS*NH + h4;
  float4 acc = make_float4(0.f,0.f,0.f,0.f);
  #pragma unroll 4
  for (int s = 0; s < NS; s++){
    uint2 u = *(const uint2*)(ep + (size_t)s*NH);
    float2 f01 = __half22float2(*(__half2*)&u.x);
    float2 f23 = __half22float2(*(__half2*)&u.y);
    float a = sa[s];
    acc.x += a*f01.x; acc.y += a*f01.y; acc.z += a*f23.x; acc.w += a*f23.y;
  }
  *(float4*)(ctx + b*NH + h4) = acc;
  *(float4*)(x0 + (size_t)b*(NE+2*NH) + NE + h4) = acc;
  uint2 h;
  h.x = packh2(make_float2(acc.x, acc.y));
  h.y = packh2(make_float2(acc.z, acc.w));
  *(uint2*)(cat2h + (size_t)b*2*NH + NH + h4) = h;
}

__global__ void prep_k(const int* __restrict__ tok, const float* __restrict__ emb,
                       const float* __restrict__ hidden,
                       float* __restrict__ x0, float* __restrict__ x1){
  int i = blockIdx.x*256 + threadIdx.x;
  if (i < NB*NE){
    int b = i >> 9, j = i & 511;
    x0[(size_t)b*(NE+2*NH) + j] = emb[(size_t)tok[b]*NE + j];
  } else if (i < NB*(NE+NH)){
    int t = i - NB*NE; int b = t >> 10, j = t & 1023;
    x0[(size_t)b*(NE+2*NH) + NE + NH + j] = hidden[b*NH + j];
  } else {
    int t = i - NB*(NE+NH); int b = t >> 10, j = t & 1023;
    x1[(size_t)b*2*NH + NH + j] = hidden[(size_t)NB*NH + b*NH + j];
  }
}

// sums 8 split-K gate partials + biases, applies LSTM cell.
// h -> hout (output) and optionally fp32 hout2 (x1) / fp16 hout2h (cat2h).
__global__ void lstm_k(const float* __restrict__ gp, const float* __restrict__ bih,
                       const float* __restrict__ bhh, const float* __restrict__ cprev,
                       float* __restrict__ hout, float* __restrict__ cout,
                       float* __restrict__ hout2, __half* __restrict__ hout2h){
  int i = blockIdx.x*256 + threadIdx.x;
  int b = i >> 10, h = i & 1023;
  const size_t base = (size_t)b*4*NH;
  float ig = bih[h]      + bhh[h];
  float fg = bih[NH+h]   + bhh[NH+h];
  float gg = bih[2*NH+h] + bhh[2*NH+h];
  float og = bih[3*NH+h] + bhh[3*NH+h];
  #pragma unroll
  for (int p = 0; p < 8; p++){
    const float* gr = gp + (size_t)p*NB*4*NH + base;
    ig += gr[h]; fg += gr[NH+h]; gg += gr[2*NH+h]; og += gr[3*NH+h];
  }
  float si = 1.f/(1.f+expf(-ig));
  float sf = 1.f/(1.f+expf(-fg));
  float so = 1.f/(1.f+expf(-og));
  float cn = sf*cprev[i] + si*tanhf(gg);
  float hv = so*tanhf(cn);
  cout[i] = cn;
  hout[i] = hv;
  if (hout2)  hout2[(size_t)b*2*NH + h] = hv;
  if (hout2h) hout2h[(size_t)b*2*NH + h] = __float2half_rn(hv);
}

// log_softmax over 2 fc split-K partials (+bias)
__global__ void __launch_bounds__(1024) logsoftmax2_k(const float* __restrict__ fp,
                                                      const float* __restrict__ fcb,
                                                      float* __restrict__ pred){
  __shared__ float red[32];
  const int b = blockIdx.x, tid = threadIdx.x;
  const float* r0 = fp + (size_t)b*NV;
  const float* r1 = fp + (size_t)NB*NV + (size_t)b*NV;
  float* row = pred + (size_t)b*NV;

  float m = -1e30f;
  for (int i = tid; i < NV; i += 1024){
    float v = r0[i] + r1[i] + fcb[i];
    row[i] = v;
    m = fmaxf(m, v);
  }
  #pragma unroll
  for (int o = 16; o > 0; o >>= 1) m = fmaxf(m, __shfl_xor_sync(0xffffffffu, m, o));
  if ((tid&31)==0) red[tid>>5] = m;
  __syncthreads();
  if (tid < 32){
    float x = red[tid];
    #pragma unroll
    for (int o = 16; o > 0; o >>= 1) x = fmaxf(x, __shfl_xor_sync(0xffffffffu, x, o));
    if (tid == 0) red[0] = x;
  }
  __syncthreads();
  const float bm = red[0];
  __syncthreads();
  float s = 0.f;
  for (int i = tid; i < NV; i += 1024) s += expf(row[i] - bm);
  #pragma unroll
  for (int o = 16; o > 0; o >>= 1) s += __shfl_xor_sync(0xffffffffu, s, o);
  if ((tid&31)==0) red[tid>>5] = s;
  __syncthreads();
  if (tid < 32){
    float x = red[tid];
    #pragma unroll
    for (int o = 16; o > 0; o >>= 1) x += __shfl_xor_sync(0xffffffffu, x, o);
    if (tid == 0) red[0] = x;
  }
  __syncthreads();
  const float lg = bm + logf(red[0]);
  for (int i = tid; i < NV; i += 1024) row[i] = row[i] - lg;
}

// ================= launcher =================
extern "C" void kernel_launch(void* const* d_in, const int* in_sizes, int n_in,
                              void* d_out, int out_size){
  const int*   tok   = (const int*)  d_in[0];
  const float* hidden= (const float*)d_in[1];
  const float* cell  = (const float*)d_in[2];
  const float* enc   = (const float*)d_in[3];
  const float* emb   = (const float*)d_in[4];
  const float* W1w   = (const float*)d_in[5];
  const float* W1b   = (const float*)d_in[6];
  const float* W2w   = (const float*)d_in[7];
  const float* W2b   = (const float*)d_in[8];
  const float* Vw    = (const float*)d_in[9];
  const float* Vb    = (const float*)d_in[10];
  const float* wih0  = (const float*)d_in[11];
  const float* whh0  = (const float*)d_in[12];
  const float* bih0  = (const float*)d_in[13];
  const float* bhh0  = (const float*)d_in[14];
  const float* wih1  = (const float*)d_in[15];
  const float* whh1  = (const float*)d_in[16];
  const float* bih1  = (const float*)d_in[17];
  const float* bhh1  = (const float*)d_in[18];
  const float* fcw   = (const float*)d_in[19];
  const float* fcb   = (const float*)d_in[20];

  float* out    = (float*)d_out;
  float* pred   = out + OFF_PRED;
  float* hid_o  = out + OFF_HID;
  float* cell_o = out + OFF_CELL;
  float* attn_o = out + OFF_ATTN;

  __half *ench, *w1h, *fcwh, *cat2h;
  float *q, *qp, *spart, *ctx, *x0, *x1, *gp, *fcp;
  cudaGetSymbolAddress((void**)&ench,   g_ench);
  cudaGetSymbolAddress((void**)&w1h,    g_w1h);
  cudaGetSymbolAddress((void**)&fcwh,   g_fcwh);
  cudaGetSymbolAddress((void**)&cat2h,  g_cat2h);
  cudaGetSymbolAddress((void**)&q,      g_q);
  cudaGetSymbolAddress((void**)&qp,     g_qpart);
  cudaGetSymbolAddress((void**)&spart,  g_spart);
  cudaGetSymbolAddress((void**)&ctx,    g_context);
  cudaGetSymbolAddress((void**)&x0,     g_x0);
  cudaGetSymbolAddress((void**)&x1,     g_x1);
  cudaGetSymbolAddress((void**)&gp,     g_gpart);
  cudaGetSymbolAddress((void**)&fcp,    g_fcpart);

  static cudaStream_t sC = nullptr;
  static cudaEvent_t eF = nullptr, eC = nullptr;
  if (!sC){
    cudaStreamCreateWithFlags(&sC, cudaStreamNonBlocking);
    cudaEventCreateWithFlags(&eF, cudaEventDisableTiming);
    cudaEventCreateWithFlags(&eC, cudaEventDisableTiming);
  }

  const int smHN = (128+256)*80*3;       // 92160 B (fp16-native)
  const int smC128 = (128+128)*48*2;     // 24576 B (inline, BN=128)
  cudaFuncSetAttribute(gemm16h<256,EPI_ATTN>,  cudaFuncAttributeMaxDynamicSharedMemorySize, smHN);
  cudaFuncSetAttribute(gemm16h<256,EPI_STORE>, cudaFuncAttributeMaxDynamicSharedMemorySize, smHN);
  cudaFuncSetAttribute(gemm16<128,EPI_STORE>,  cudaFuncAttributeMaxDynamicSharedMemorySize, smC128);

  // ---- fork: big fcw conversion runs in the shadow of the whole pipeline ----
  cudaEventRecord(eF, 0);
  cudaStreamWaitEvent(sC, eF, 0);
  conv_gs_k<<<2048, 256, 0, sC>>>((const float4*)fcw, (uint2*)fcwh, NV*2*NH/4);
  cudaEventRecord(eC, sC);

  // 0) fp16 pre-conversion: enc + W1
  conv_k<<<(NB*NS*NH/4)/256, 256>>>((const float4*)enc, (uint2*)ench, NB*NS*NH/4);
  conv_k<<<(NH*NH/4)/256, 256>>>((const float4*)W1w, (uint2*)w1h, NH*NH/4);

  // 0b) prep x0/x1 static parts
  prep_k<<<(NB*(NE+2*NH))/256, 256>>>(tok, emb, hidden, x0, x1);

  // 1) q partials: h_top @ W2^T (split-K 8)
  gemm16<128,EPI_STORE><<<dim3(NH/128,1,8), 256, smC128>>>(
      hidden + (size_t)NB*NH, W2w, W2w, NH, qp, NB, NH, NH, NH/8,
      nullptr, nullptr, nullptr, nullptr);
  reduce_q_k<<<(NB*NH)/256, 256>>>(qp, W2b, q);

  // 2) fused energy + score partials (fp16-native, 8 warps)
  gemm16h<256,EPI_ATTN><<<dim3(NH/256, (NB*NS)/128, 1), 256, smHN>>>(
      ench, w1h, nullptr, NB*NS, NH, NH, NH, W1b, q, Vw, spart);

  // 3) score reduce + softmax
  softmax_fused_k<<<NB, NS>>>(spart, Vb, attn_o);

  // 4) context (fp16 enc; scatters to x0 fp32, cat2h fp16)
  ctx_k<<<dim3(NB, NH/512), 128>>>(attn_o, ench, ctx, x0, cat2h);

  // 5) gates0 partials: x0 @ [wih0|whh0]^T (split-K 8)
  gemm16<128,EPI_STORE><<<dim3(4*NH/128,1,8), 256, smC128>>>(
      x0, wih0, whh0, NE+NH, gp, NB, 4*NH, NE+2*NH, (NE+2*NH)/8,
      nullptr, nullptr, nullptr, nullptr);

  // 6) LSTM cell 0 (h0 -> hid_o + x1 fp32)
  lstm_k<<<(NB*NH)/256, 256>>>(gp, bih0, bhh0, cell, hid_o, cell_o, x1, nullptr);

  // 7) gates1 partials: x1 @ [wih1|whh1]^T (split-K 8)
  gemm16<128,EPI_STORE><<<dim3(4*NH/128,1,8), 256, smC128>>>(
      x1, wih1, whh1, NH, gp, NB, 4*NH, 2*NH, (2*NH)/8,
      nullptr, nullptr, nullptr, nullptr);

  // 8) LSTM cell 1 (h1 -> hid_o + cat2h fp16)
  lstm_k<<<(NB*NH)/256, 256>>>(gp, bih1, bhh1, cell + (size_t)NB*NH,
                               hid_o + (size_t)NB*NH, cell_o + (size_t)NB*NH,
                               nullptr, cat2h);

  // join: fcw fp16 must be ready
  cudaStreamWaitEvent(0, eC, 0);

  // 9) fc partials: cat2h @ fcwh^T (fp16-native, split-K 2)
  gemm16h<256,EPI_STORE><<<dim3(NV/256,1,2), 256, smHN>>>(
      cat2h, fcwh, fcp, NB, NV, 2*NH, NH,
      nullptr, nullptr, nullptr, nullptr);

  // 10) 2-partial sum + bias + log_softmax
  logsoftmax2_k<<<NB, 1024>>>(fcp, fcb, pred);
}

// round 15
// speedup vs baseline: 1.1070x; 1.1070x over previous
#include <cuda_runtime.h>
#include <cstdint>
#include <cuda_fp16.h>

#define NB 128
#define NS 256
#define NH 1024
#define NE 512
#define NV 32000
#define NL 2

#define OFF_PRED 0
#define OFF_HID  (NB*NV)
#define OFF_CELL (OFF_HID + NL*NB*NH)
#define OFF_ATTN (OFF_CELL + NL*NB*NH)

#define EPI_STORE 0
#define EPI_ATTN  2

// -------- device scratch --------
__device__ __align__(16) __half g_ench[NB*NS*NH];    // fp16 encoder (67MB)
__device__ __align__(16) __half g_w1h[NH*NH];        // fp16 W1
__device__ __align__(16) float g_q[NB*NH];
__device__ __align__(16) float g_qpart[8*NB*NH];
__device__ __align__(16) float g_spart[8*NB*NS];     // 8 n-slabs now
__device__ __align__(16) float g_context[NB*NH];
__device__ __align__(16) float g_x0[NB*(NE+2*NH)];   // [emb, ctx, h0_prev]
__device__ __align__(16) float g_x1[NB*2*NH];        // [h0_new, h1_prev]
__device__ __align__(16) float g_gpart[8*NB*4*NH];
__device__ __align__(16) float g_cat2[NB*2*NH];      // [h1_new, ctx]
__device__ __align__(16) float g_fcpart[2*NB*NV];

__device__ __forceinline__ uint32_t smem_u32(const void* p){
  uint32_t a; asm("{ .reg .u64 t; cvta.to.shared.u64 t, %1; cvt.u32.u64 %0, t; }" : "=r"(a) : "l"(p));
  return a;
}
__device__ __forceinline__ uint32_t packh2(float2 v){
  uint32_t r; asm("cvt.rn.f16x2.f32 %0, %1, %2;" : "=r"(r) : "f"(v.y), "f"(v.x)); return r;
}
__device__ __forceinline__ void mma16(float* d, const uint32_t* a, const uint32_t* b){
  asm volatile("mma.sync.aligned.m16n8k16.row.col.f32.f16.f16.f32 "
    "{%0,%1,%2,%3},{%4,%5,%6,%7},{%8,%9},{%0,%1,%2,%3};"
    : "+f"(d[0]),"+f"(d[1]),"+f"(d[2]),"+f"(d[3])
    : "r"(a[0]),"r"(a[1]),"r"(a[2]),"r"(a[3]),"r"(b[0]),"r"(b[1]));
}
__device__ __forceinline__ void ldsm4(uint32_t& r0,uint32_t& r1,uint32_t& r2,uint32_t& r3, uint32_t addr){
  asm volatile("ldmatrix.sync.aligned.m8n8.x4.shared.b16 {%0,%1,%2,%3}, [%4];"
    : "=r"(r0),"=r"(r1),"=r"(r2),"=r"(r3) : "r"(addr));
}

// ============ fp16-NATIVE GEMM (attention): C(M,N)=A(M,K)@B(N,K)^T ============
// BN=128, 256 threads / 8 warps, 2 CTAs per SM (independent barriers hide
// per-ktile sync latency). cp.async direct, BK=32, 3 stages.
template<int BN, int EPI>
__global__ void __launch_bounds__(256,2) gemm16h(
    const __half* __restrict__ A, const __half* __restrict__ B,
    float* __restrict__ C, int M, int N, int K,
    const float* __restrict__ bias,
    const float* __restrict__ qv, const float* __restrict__ vw, float* __restrict__ spart)
{
  constexpr int BM = 128, BK = 32, NSTG = 3;
  constexpr int WN = BN/4, NF = WN/8, NPB = NF/2;   // BN=128: WN=32, NF=4, NPB=2
  constexpr int RSB = 80;
  constexpr int STAGE = (BM+BN)*RSB;
  constexpr int CPT = (BM+BN)*4/256;

  extern __shared__ char dsm[];
  __shared__ float sBias[BN], sQ[BN], sVw[BN];
  __shared__ float srow[BM];

  const uint32_t smb = smem_u32(dsm);
  const int tid = threadIdx.x, warp = tid>>5, lane = tid&31;
  const int g = lane>>2, tq = lane&3;
  const int wm = (warp&1)*64, wn = (warp>>1)*WN;
  const size_t m0 = (size_t)blockIdx.y*BM;
  const int n0 = blockIdx.x*BN;
  const int kt = K/BK;

  if (tid < BN){
    sBias[tid] = bias ? bias[n0+tid] : 0.f;
    if (EPI == EPI_ATTN){ sVw[tid] = vw[n0+tid]; sQ[tid] = qv[(m0/NS)*NH + n0 + tid]; }
  }
  if (EPI == EPI_ATTN && tid < BM) srow[tid] = 0.f;

  uint32_t offA[4], offB[NPB];
  {
    int rA = (lane & 15), kcA = (lane >> 4) * 16;
    #pragma unroll
    for (int mt = 0; mt < 4; mt++) offA[mt] = (uint32_t)((wm + mt*16 + rA)*RSB + kcA);
    int rB = (lane & 7) + ((lane >= 16) ? 8 : 0), kcB = ((lane >> 3) & 1) * 16;
    #pragma unroll
    for (int np = 0; np < NPB; np++) offB[np] = (uint32_t)((BM + wn + np*16 + rB)*RSB + kcB);
  }

  float acc[4][NF][4];
  #pragma unroll
  for (int i=0;i<4;i++)
    #pragma unroll
    for (int j=0;j<NF;j++)
      #pragma unroll
      for (int k=0;k<4;k++) acc[i][j][k]=0.f;

  auto fill = [&](int s, int t){
    const uint32_t base = smb + (uint32_t)s*STAGE;
    const int k0 = t*BK;
    #pragma unroll
    for (int i = 0; i < CPT; i++){
      int c = tid + i*256;
      int row = c>>2, q = c&3;
      const __half* src = (row < BM)
        ? A + (m0 + row)*(size_t)K + k0 + q*8
        : B + (size_t)(n0 + row - BM)*K + k0 + q*8;
      uint32_t dst = base + (uint32_t)(row*RSB + q*16);
      asm volatile("cp.async.cg.shared.global [%0], [%1], 16;" :: "r"(dst), "l"(src) : "memory");
    }
    asm volatile("cp.async.commit_group;" ::: "memory");
  };

  fill(0,0); fill(1,1);

  for (int j = 0; j < kt; j++){
    asm volatile("cp.async.wait_group 1;" ::: "memory");
    __syncthreads();
    if (j+2 < kt) fill((j+2)%NSTG, j+2);
    else asm volatile("cp.async.commit_group;" ::: "memory");

    const uint32_t sb = smb + (uint32_t)(j%NSTG)*STAGE;
    #pragma unroll
    for (int ks = 0; ks < 2; ks++){
      uint32_t af[4][4], bf[NF][2];
      #pragma unroll
      for (int mt = 0; mt < 4; mt++)
        ldsm4(af[mt][0], af[mt][1], af[mt][2], af[mt][3], sb + offA[mt] + ks*32);
      #pragma unroll
      for (int np = 0; np < NPB; np++)
        ldsm4(bf[2*np][0], bf[2*np][1], bf[2*np+1][0], bf[2*np+1][1], sb + offB[np] + ks*32);
      #pragma unroll
      for (int mt = 0; mt < 4; mt++)
        #pragma unroll
        for (int nt = 0; nt < NF; nt++)
          mma16(acc[mt][nt], af[mt], bf[nt]);
    }
  }

  if (EPI == EPI_ATTN){
    __syncthreads();
    #pragma unroll
    for (int mt = 0; mt < 4; mt++){
      float p0 = 0.f, p1 = 0.f;
      #pragma unroll
      for (int nt = 0; nt < NF; nt++){
        int c = wn + nt*8 + 2*tq;
        float b0 = sBias[c]   + sQ[c];
        float b1 = sBias[c+1] + sQ[c+1];
        float v0 = sVw[c], v1 = sVw[c+1];
        p0 += tanhf(acc[mt][nt][0]+b0)*v0 + tanhf(acc[mt][nt][1]+b1)*v1;
        p1 += tanhf(acc[mt][nt][2]+b0)*v0 + tanhf(acc[mt][nt][3]+b1)*v1;
      }
      p0 += __shfl_xor_sync(0xffffffffu, p0, 1);
      p0 += __shfl_xor_sync(0xffffffffu, p0, 2);
      p1 += __shfl_xor_sync(0xffffffffu, p1, 1);
      p1 += __shfl_xor_sync(0xffffffffu, p1, 2);
      if (tq == 0){
        atomicAdd(&srow[wm+mt*16+g  ], p0);
        atomicAdd(&srow[wm+mt*16+g+8], p1);
      }
    }
    __syncthreads();
    if (tid < BM) spart[(size_t)blockIdx.x*M + m0 + tid] = srow[tid];
  } else {
    #pragma unroll
    for (int mt = 0; mt < 4; mt++){
      #pragma unroll
      for (int nt = 0; nt < NF; nt++){
        size_t r = m0 + wm + mt*16 + g;
        int c = n0 + wn + nt*8 + 2*tq;
        float b0 = sBias[c - n0], b1 = sBias[c - n0 + 1];
        float2* p0 = (float2*)(C + r*N + c);
        float2* p1 = (float2*)(C + (r+8)*N + c);
        *p0 = make_float2(acc[mt][nt][0]+b0, acc[mt][nt][1]+b1);
        *p1 = make_float2(acc[mt][nt][2]+b0, acc[mt][nt][3]+b1);
      }
    }
  }
}

// ============ fp32-input GEMM (inline cvt, proven R7 ordering) ============
template<int BN, int EPI>
__global__ void __launch_bounds__(256,1) gemm16(
    const float* __restrict__ A, const float* __restrict__ B1, const float* __restrict__ B2,
    int Ksplit, float* __restrict__ C, int M, int N, int K, int kLen,
    const float* __restrict__ bias,
    const float* __restrict__ qv, const float* __restrict__ vw, float* __restrict__ spart)
{
  constexpr int BM = 128, BK = 16;
  constexpr int WN = BN/4, NF = WN/8, NPB = NF/2;
  constexpr int RSB = 48;
  constexpr int STAGE = (BM+BN)*RSB;
  constexpr int NLD = (BM+BN)*4/256;

  extern __shared__ char dsm[];
  __shared__ float sBias[BN];
  const uint32_t smb = smem_u32(dsm);
  const int tid = threadIdx.x, warp = tid>>5, lane = tid&31;
  const int g = lane>>2, tq = lane&3;
  const int wm = (warp&1)*64, wn = (warp>>1)*WN;
  const size_t m0 = (size_t)blockIdx.y*BM;
  const int n0 = blockIdx.x*BN;
  const int kOff = blockIdx.z*kLen;
  const int kt = kLen/BK;
  const int K2 = K - Ksplit;

  if (tid < BN) sBias[tid] = bias ? bias[n0+tid] : 0.f;

  uint32_t offA[4], offB[NPB];
  {
    int rA = (lane & 15), kcA = (lane >> 4) * 16;
    #pragma unroll
    for (int mt = 0; mt < 4; mt++) offA[mt] = (uint32_t)((wm + mt*16 + rA)*RSB + kcA);
    int rB = (lane & 7) + ((lane >= 16) ? 8 : 0), kcB = ((lane >> 3) & 1) * 16;
    #pragma unroll
    for (int np = 0; np < NPB; np++) offB[np] = (uint32_t)((BM + wn + np*16 + rB)*RSB + kcB);
  }

  float acc[4][NF][4];
  #pragma unroll
  for (int i=0;i<4;i++)
    #pragma unroll
    for (int j=0;j<NF;j++)
      #pragma unroll
      for (int k=0;k<4;k++) acc[i][j][k]=0.f;

  float4 v[NLD];
  int rown[NLD], quad[NLD];
  #pragma unroll
  for (int i = 0; i < NLD; i++){ int c = tid + i*256; rown[i] = c>>2; quad[i] = c&3; }

  auto ldg = [&](int t){
    const int k0 = kOff + t*BK;
    #pragma unroll
    for (int i = 0; i < NLD; i++){
      int kg = k0 + quad[i]*4;
      const float* src;
      if (rown[i] < BM) src = A + (m0 + rown[i])*(size_t)K + kg;
      else {
        int n = n0 + rown[i] - BM;
        if (kg < Ksplit) src = B1 + (size_t)n*Ksplit + kg;
        else             src = B2 + (size_t)n*K2 + (kg - Ksplit);
      }
      v[i] = *(const float4*)src;
    }
  };
  auto sts = [&](int s){
    const uint32_t base = smb + (uint32_t)s*STAGE;
    #pragma unroll
    for (int i = 0; i < NLD; i++){
      uint32_t lo = packh2(make_float2(v[i].x, v[i].y));
      uint32_t hi = packh2(make_float2(v[i].z, v[i].w));
      uint32_t dst = base + (uint32_t)(rown[i]*RSB + quad[i]*8);
      asm volatile("st.shared.v2.u32 [%0], {%1,%2};" :: "r"(dst), "r"(lo), "r"(hi) : "memory");
    }
  };

  ldg(0); sts(0);
  if (kt > 1) ldg(1);
  __syncthreads();

  for (int j = 0; j < kt; j++){
    const uint32_t sb = smb + (uint32_t)(j&1)*STAGE;
    uint32_t af[4][4], bf[NF][2];
    #pragma unroll
    for (int mt = 0; mt < 4; mt++)
      ldsm4(af[mt][0], af[mt][1], af[mt][2], af[mt][3], sb + offA[mt]);
    #pragma unroll
    for (int np = 0; np < NPB; np++)
      ldsm4(bf[2*np][0], bf[2*np][1], bf[2*np+1][0], bf[2*np+1][1], sb + offB[np]);
    #pragma unroll
    for (int mt = 0; mt < 4; mt++)
      #pragma unroll
      for (int nt = 0; nt < NF; nt++)
        mma16(acc[mt][nt], af[mt], bf[nt]);
    if (j+1 < kt){
      sts((j+1)&1);
      if (j+2 < kt) ldg(j+2);
    }
    __syncthreads();
  }

  float* Cz = C + (size_t)blockIdx.z*M*N;
  #pragma unroll
  for (int mt = 0; mt < 4; mt++){
    #pragma unroll
    for (int nt = 0; nt < NF; nt++){
      size_t r = m0 + wm + mt*16 + g;
      int c = n0 + wn + nt*8 + 2*tq;
      float b0 = sBias[c - n0], b1 = sBias[c - n0 + 1];
      float2* p0 = (float2*)(Cz + r*N + c);
      float2* p1 = (float2*)(Cz + (r+8)*N + c);
      *p0 = make_float2(acc[mt][nt][0]+b0, acc[mt][nt][1]+b1);
      *p1 = make_float2(acc[mt][nt][2]+b0, acc[mt][nt][3]+b1);
    }
  }
}

// ================= small kernels =================
__global__ void conv_k(const float4* __restrict__ src, uint2* __restrict__ dst, int n4){
  int i = blockIdx.x*256 + threadIdx.x;
  if (i >= n4) return;
  float4 v = src[i];
  uint2 o;
  o.x = packh2(make_float2(v.x, v.y));
  o.y = packh2(make_float2(v.z, v.w));
  dst[i] = o;
}

__global__ void reduce_q_k(const float* __restrict__ qp, const float* __restrict__ w2b,
                           float* __restrict__ q){
  int i = blockIdx.x*256 + threadIdx.x;
  float s = w2b[i & (NH-1)];
  #pragma unroll
  for (int p = 0; p < 8; p++) s += qp[(size_t)p*NB*NH + i];
  q[i] = s;
}

// sums 8 n-slab score partials (+V_b) then softmax over S
__global__ void __launch_bounds__(NS) softmax_fused_k(const float* __restrict__ spart,
                                                      const float* __restrict__ vb,
                                                      float* __restrict__ attn_out){
  __shared__ float red[8];
  const int b = blockIdx.x, tid = threadIdx.x;
  const int m = b*NS + tid;
  float v = vb[0];
  #pragma unroll
  for (int j = 0; j < 8; j++) v += spart[(size_t)j*(NB*NS) + m];

  float mx = v;
  #pragma unroll
  for (int o = 16; o > 0; o >>= 1) mx = fmaxf(mx, __shfl_xor_sync(0xffffffffu, mx, o));
  if ((tid&31)==0) red[tid>>5] = mx;
  __syncthreads();
  if (tid == 0){ float x = red[0]; for (int i=1;i<8;i++) x = fmaxf(x, red[i]); red[0] = x; }
  __syncthreads();
  const float bm = red[0];
  __syncthreads();
  float e = expf(v - bm), s = e;
  #pragma unroll
  for (int o = 16; o > 0; o >>= 1) s += __shfl_xor_sync(0xffffffffu, s, o);
  if ((tid&31)==0) red[tid>>5] = s;
  __syncthreads();
  if (tid == 0){ float x = 0.f; for (int i=0;i<8;i++) x += red[i]; red[0] = x; }
  __syncthreads();
  attn_out[m] = e / red[0];
}

// context from fp16 enc; scatters into ctx, x0 slot, cat2 slot
__global__ void __launch_bounds__(128) ctx_k(const float* __restrict__ attn,
                                             const __half* __restrict__ ench,
                                             float* __restrict__ ctx,
                                             float* __restrict__ x0,
                                             float* __restrict__ cat2){
  __shared__ float sa[NS];
  const int b = blockIdx.x, hc = blockIdx.y, tid = threadIdx.x;
  sa[tid]     = attn[b*NS + tid];
  sa[tid+128] = attn[b*NS + tid + 128];
  __syncthreads();
  const int h4 = hc*512 + tid*4;
  const __half* ep = ench + (size_t)b*NS*NH + h4;
  float4 acc = make_float4(0.f,0.f,0.f,0.f);
  #pragma unroll 4
  for (int s = 0; s < NS; s++){
    uint2 u = *(const uint2*)(ep + (size_t)s*NH);
    float2 f01 = __half22float2(*(__half2*)&u.x);
    float2 f23 = __half22float2(*(__half2*)&u.y);
    float a = sa[s];
    acc.x += a*f01.x; acc.y += a*f01.y; acc.z += a*f23.x; acc.w += a*f23.y;
  }
  *(float4*)(ctx + b*NH + h4) = acc;
  *(float4*)(x0 + (size_t)b*(NE+2*NH) + NE + h4) = acc;
  *(float4*)(cat2 + (size_t)b*2*NH + NH + h4) = acc;
}

__global__ void prep_k(const int* __restrict__ tok, const float* __restrict__ emb,
                       const float* __restrict__ hidden,
                       float* __restrict__ x0, float* __restrict__ x1){
  int i = blockIdx.x*256 + threadIdx.x;
  if (i < NB*NE){
    int b = i >> 9, j = i & 511;
    x0[(size_t)b*(NE+2*NH) + j] = emb[(size_t)tok[b]*NE + j];
  } else if (i < NB*(NE+NH)){
    int t = i - NB*NE; int b = t >> 10, j = t & 1023;
    x0[(size_t)b*(NE+2*NH) + NE + NH + j] = hidden[b*NH + j];
  } else {
    int t = i - NB*(NE+NH); int b = t >> 10, j = t & 1023;
    x1[(size_t)b*2*NH + NH + j] = hidden[(size_t)NB*NH + b*NH + j];
  }
}

// sums 8 split-K gate partials + biases, applies LSTM cell; writes h to 2 dests
__global__ void lstm_k(const float* __restrict__ gp, const float* __restrict__ bih,
                       const float* __restrict__ bhh, const float* __restrict__ cprev,
                       float* __restrict__ hout, float* __restrict__ cout,
                       float* __restrict__ hout2){
  int i = blockIdx.x*256 + threadIdx.x;
  int b = i >> 10, h = i & 1023;
  const size_t base = (size_t)b*4*NH;
  float ig = bih[h]      + bhh[h];
  float fg = bih[NH+h]   + bhh[NH+h];
  float gg = bih[2*NH+h] + bhh[2*NH+h];
  float og = bih[3*NH+h] + bhh[3*NH+h];
  #pragma unroll
  for (int p = 0; p < 8; p++){
    const float* gr = gp + (size_t)p*NB*4*NH + base;
    ig += gr[h]; fg += gr[NH+h]; gg += gr[2*NH+h]; og += gr[3*NH+h];
  }
  float si = 1.f/(1.f+expf(-ig));
  float sf = 1.f/(1.f+expf(-fg));
  float so = 1.f/(1.f+expf(-og));
  float cn = sf*cprev[i] + si*tanhf(gg);
  float hv = so*tanhf(cn);
  cout[i] = cn;
  hout[i] = hv;
  hout2[(size_t)b*2*NH + h] = hv;
}

// log_softmax over 2 fc split-K partials (+bias)
__global__ void __launch_bounds__(1024) logsoftmax2_k(const float* __restrict__ fp,
                                                      const float* __restrict__ fcb,
                                                      float* __restrict__ pred){
  __shared__ float red[32];
  const int b = blockIdx.x, tid = threadIdx.x;
  const float* r0 = fp + (size_t)b*NV;
  const float* r1 = fp + (size_t)NB*NV + (size_t)b*NV;
  float* row = pred + (size_t)b*NV;

  float m = -1e30f;
  for (int i = tid; i < NV; i += 1024){
    float v = r0[i] + r1[i] + fcb[i];
    row[i] = v;
    m = fmaxf(m, v);
  }
  #pragma unroll
  for (int o = 16; o > 0; o >>= 1) m = fmaxf(m, __shfl_xor_sync(0xffffffffu, m, o));
  if ((tid&31)==0) red[tid>>5] = m;
  __syncthreads();
  if (tid < 32){
    float x = red[tid];
    #pragma unroll
    for (int o = 16; o > 0; o >>= 1) x = fmaxf(x, __shfl_xor_sync(0xffffffffu, x, o));
    if (tid == 0) red[0] = x;
  }
  __syncthreads();
  const float bm = red[0];
  __syncthreads();
  float s = 0.f;
  for (int i = tid; i < NV; i += 1024) s += expf(row[i] - bm);
  #pragma unroll
  for (int o = 16; o > 0; o >>= 1) s += __shfl_xor_sync(0xffffffffu, s, o);
  if ((tid&31)==0) red[tid>>5] = s;
  __syncthreads();
  if (tid < 32){
    float x = red[tid];
    #pragma unroll
    for (int o = 16; o > 0; o >>= 1) x += __shfl_xor_sync(0xffffffffu, x, o);
    if (tid == 0) red[0] = x;
  }
  __syncthreads();
  const float lg = bm + logf(red[0]);
  for (int i = tid; i < NV; i += 1024) row[i] = row[i] - lg;
}

// ================= launcher =================
extern "C" void kernel_launch(void* const* d_in, const int* in_sizes, int n_in,
                              void* d_out, int out_size){
  const int*   tok   = (const int*)  d_in[0];
  const float* hidden= (const float*)d_in[1];
  const float* cell  = (const float*)d_in[2];
  const float* enc   = (const float*)d_in[3];
  const float* emb   = (const float*)d_in[4];
  const float* W1w   = (const float*)d_in[5];
  const float* W1b   = (const float*)d_in[6];
  const float* W2w   = (const float*)d_in[7];
  const float* W2b   = (const float*)d_in[8];
  const float* Vw    = (const float*)d_in[9];
  const float* Vb    = (const float*)d_in[10];
  const float* wih0  = (const float*)d_in[11];
  const float* whh0  = (const float*)d_in[12];
  const float* bih0  = (const float*)d_in[13];
  const float* bhh0  = (const float*)d_in[14];
  const float* wih1  = (const float*)d_in[15];
  const float* whh1  = (const float*)d_in[16];
  const float* bih1  = (const float*)d_in[17];
  const float* bhh1  = (const float*)d_in[18];
  const float* fcw   = (const float*)d_in[19];
  const float* fcb   = (const float*)d_in[20];

  float* out    = (float*)d_out;
  float* pred   = out + OFF_PRED;
  float* hid_o  = out + OFF_HID;
  float* cell_o = out + OFF_CELL;
  float* attn_o = out + OFF_ATTN;

  __half *ench, *w1h;
  float *q, *qp, *spart, *ctx, *x0, *x1, *gp, *cat2, *fcp;
  cudaGetSymbolAddress((void**)&ench,   g_ench);
  cudaGetSymbolAddress((void**)&w1h,    g_w1h);
  cudaGetSymbolAddress((void**)&q,      g_q);
  cudaGetSymbolAddress((void**)&qp,     g_qpart);
  cudaGetSymbolAddress((void**)&spart,  g_spart);
  cudaGetSymbolAddress((void**)&ctx,    g_context);
  cudaGetSymbolAddress((void**)&x0,     g_x0);
  cudaGetSymbolAddress((void**)&x1,     g_x1);
  cudaGetSymbolAddress((void**)&gp,     g_gpart);
  cudaGetSymbolAddress((void**)&cat2,   g_cat2);
  cudaGetSymbolAddress((void**)&fcp,    g_fcpart);

  const int smHN = (128+128)*80*3;       // 61440 B (fp16-native, BN=128, occ 2)
  const int smC256 = (128+256)*48*2;     // 36864 B (inline, BN=256)
  const int smC128 = (128+128)*48*2;     // 24576 B (inline, BN=128)
  cudaFuncSetAttribute(gemm16h<128,EPI_ATTN>, cudaFuncAttributeMaxDynamicSharedMemorySize, smHN);
  cudaFuncSetAttribute(gemm16<256,EPI_STORE>, cudaFuncAttributeMaxDynamicSharedMemorySize, smC256);
  cudaFuncSetAttribute(gemm16<128,EPI_STORE>, cudaFuncAttributeMaxDynamicSharedMemorySize, smC128);

  // 0) fp16 pre-conversion: enc + W1
  conv_k<<<(NB*NS*NH/4)/256, 256>>>((const float4*)enc, (uint2*)ench, NB*NS*NH/4);
  conv_k<<<(NH*NH/4)/256, 256>>>((const float4*)W1w, (uint2*)w1h, NH*NH/4);

  // 0b) prep x0/x1 static parts
  prep_k<<<(NB*(NE+2*NH))/256, 256>>>(tok, emb, hidden, x0, x1);

  // 1) q partials: h_top @ W2^T (split-K 8)
  gemm16<128,EPI_STORE><<<dim3(NH/128,1,8), 256, smC128>>>(
      hidden + (size_t)NB*NH, W2w, W2w, NH, qp, NB, NH, NH, NH/8,
      nullptr, nullptr, nullptr, nullptr);
  reduce_q_k<<<(NB*NH)/256, 256>>>(qp, W2b, q);

  // 2) fused energy + score partials (fp16-native, BN=128, 2 CTAs/SM)
  gemm16h<128,EPI_ATTN><<<dim3(NH/128, (NB*NS)/128), 256, smHN>>>(
      ench, w1h, nullptr, NB*NS, NH, NH, W1b, q, Vw, spart);

  // 3) score reduce (8 slabs) + softmax
  softmax_fused_k<<<NB, NS>>>(spart, Vb, attn_o);

  // 4) context (fp16 enc; scatters to x0, cat2)
  ctx_k<<<dim3(NB, NH/512), 128>>>(attn_o, ench, ctx, x0, cat2);

  // 5) gates0 partials: x0 @ [wih0|whh0]^T (split-K 8)
  gemm16<128,EPI_STORE><<<dim3(4*NH/128,1,8), 256, smC128>>>(
      x0, wih0, whh0, NE+NH, gp, NB, 4*NH, NE+2*NH, (NE+2*NH)/8,
      nullptr, nullptr, nullptr, nullptr);

  // 6) LSTM cell 0
  lstm_k<<<(NB*NH)/256, 256>>>(gp, bih0, bhh0, cell, hid_o, cell_o, x1);

  // 7) gates1 partials: x1 @ [wih1|whh1]^T (split-K 8)
  gemm16<128,EPI_STORE><<<dim3(4*NH/128,1,8), 256, smC128>>>(
      x1, wih1, whh1, NH, gp, NB, 4*NH, 2*NH, (2*NH)/8,
      nullptr, nullptr, nullptr, nullptr);

  // 8) LSTM cell 1
  lstm_k<<<(NB*NH)/256, 256>>>(gp, bih1, bhh1, cell + (size_t)NB*NH,
                               hid_o + (size_t)NB*NH, cell_o + (size_t)NB*NH, cat2);

  // 9) fc partials: cat2 @ fc_w^T (split-K 2, inline path — R11 proven)
  gemm16<256,EPI_STORE><<<dim3(NV/256,1,2), 256, smC256>>>(
      cat2, fcw, fcw, 2*NH, fcp, NB, NV, 2*NH, NH,
      nullptr, nullptr, nullptr, nullptr);

  // 10) 2-partial sum + bias + log_softmax
  logsoftmax2_k<<<NB, 1024>>>(fcp, fcb, pred);
}

// round 16
// speedup vs baseline: 1.1789x; 1.0650x over previous
#include <cuda_runtime.h>
#include <cstdint>
#include <cuda_fp16.h>

#define NB 128
#define NS 256
#define NH 1024
#define NE 512
#define NV 32000
#define NL 2

#define OFF_PRED 0
#define OFF_HID  (NB*NV)
#define OFF_CELL (OFF_HID + NL*NB*NH)
#define OFF_ATTN (OFF_CELL + NL*NB*NH)

#define EPI_STORE 0
#define EPI_ATTN  2

// -------- device scratch --------
__device__ __align__(16) __half g_ench[NB*NS*NH];    // fp16 encoder (67MB)
__device__ __align__(16) __half g_w1h[NH*NH];        // fp16 W1
__device__ __align__(16) float g_q[NB*NH];
__device__ __align__(16) float g_qpart[8*NB*NH];
__device__ __align__(16) float g_spart[8*NB*NS];     // 8 n-slabs
__device__ __align__(16) float g_context[NB*NH];
__device__ __align__(16) float g_x0[NB*(NE+2*NH)];   // [emb, ctx, h0_prev]
__device__ __align__(16) float g_x1[NB*2*NH];        // [h0_new, h1_prev]
__device__ __align__(16) float g_gpart[8*NB*4*NH];
__device__ __align__(16) float g_cat2[NB*2*NH];      // [h1_new, ctx]
__device__ __align__(16) float g_fcpart[2*NB*NV];

__device__ __forceinline__ uint32_t smem_u32(const void* p){
  uint32_t a; asm("{ .reg .u64 t; cvta.to.shared.u64 t, %1; cvt.u32.u64 %0, t; }" : "=r"(a) : "l"(p));
  return a;
}
__device__ __forceinline__ uint32_t packh2(float2 v){
  uint32_t r; asm("cvt.rn.f16x2.f32 %0, %1, %2;" : "=r"(r) : "f"(v.y), "f"(v.x)); return r;
}
__device__ __forceinline__ void mma16(float* d, const uint32_t* a, const uint32_t* b){
  asm volatile("mma.sync.aligned.m16n8k16.row.col.f32.f16.f16.f32 "
    "{%0,%1,%2,%3},{%4,%5,%6,%7},{%8,%9},{%0,%1,%2,%3};"
    : "+f"(d[0]),"+f"(d[1]),"+f"(d[2]),"+f"(d[3])
    : "r"(a[0]),"r"(a[1]),"r"(a[2]),"r"(a[3]),"r"(b[0]),"r"(b[1]));
}
__device__ __forceinline__ void ldsm4(uint32_t& r0,uint32_t& r1,uint32_t& r2,uint32_t& r3, uint32_t addr){
  asm volatile("ldmatrix.sync.aligned.m8n8.x4.shared.b16 {%0,%1,%2,%3}, [%4];"
    : "=r"(r0),"=r"(r1),"=r"(r2),"=r"(r3) : "r"(addr));
}

// ============ fp16-NATIVE GEMM (attention): C(M,N)=A(M,K)@B(N,K)^T ============
// BN=128, 256 threads / 8 warps, 2 CTAs/SM. cp.async direct, BK=32, 3 stages.
template<int BN, int EPI>
__global__ void __launch_bounds__(256,2) gemm16h(
    const __half* __restrict__ A, const __half* __restrict__ B,
    float* __restrict__ C, int M, int N, int K,
    const float* __restrict__ bias,
    const float* __restrict__ qv, const float* __restrict__ vw, float* __restrict__ spart)
{
  constexpr int BM = 128, BK = 32, NSTG = 3;
  constexpr int WN = BN/4, NF = WN/8, NPB = NF/2;
  constexpr int RSB = 80;
  constexpr int STAGE = (BM+BN)*RSB;
  constexpr int CPT = (BM+BN)*4/256;

  extern __shared__ char dsm[];
  __shared__ float sBias[BN], sQ[BN], sVw[BN];
  __shared__ float srow[BM];

  const uint32_t smb = smem_u32(dsm);
  const int tid = threadIdx.x, warp = tid>>5, lane = tid&31;
  const int g = lane>>2, tq = lane&3;
  const int wm = (warp&1)*64, wn = (warp>>1)*WN;
  const size_t m0 = (size_t)blockIdx.y*BM;
  const int n0 = blockIdx.x*BN;
  const int kt = K/BK;

  if (tid < BN){
    sBias[tid] = bias ? bias[n0+tid] : 0.f;
    if (EPI == EPI_ATTN){ sVw[tid] = vw[n0+tid]; sQ[tid] = qv[(m0/NS)*NH + n0 + tid]; }
  }
  if (EPI == EPI_ATTN && tid < BM) srow[tid] = 0.f;

  uint32_t offA[4], offB[NPB];
  {
    int rA = (lane & 15), kcA = (lane >> 4) * 16;
    #pragma unroll
    for (int mt = 0; mt < 4; mt++) offA[mt] = (uint32_t)((wm + mt*16 + rA)*RSB + kcA);
    int rB = (lane & 7) + ((lane >= 16) ? 8 : 0), kcB = ((lane >> 3) & 1) * 16;
    #pragma unroll
    for (int np = 0; np < NPB; np++) offB[np] = (uint32_t)((BM + wn + np*16 + rB)*RSB + kcB);
  }

  float acc[4][NF][4];
  #pragma unroll
  for (int i=0;i<4;i++)
    #pragma unroll
    for (int j=0;j<NF;j++)
      #pragma unroll
      for (int k=0;k<4;k++) acc[i][j][k]=0.f;

  auto fill = [&](int s, int t){
    const uint32_t base = smb + (uint32_t)s*STAGE;
    const int k0 = t*BK;
    #pragma unroll
    for (int i = 0; i < CPT; i++){
      int c = tid + i*256;
      int row = c>>2, q = c&3;
      const __half* src = (row < BM)
        ? A + (m0 + row)*(size_t)K + k0 + q*8
        : B + (size_t)(n0 + row - BM)*K + k0 + q*8;
      uint32_t dst = base + (uint32_t)(row*RSB + q*16);
      asm volatile("cp.async.cg.shared.global [%0], [%1], 16;" :: "r"(dst), "l"(src) : "memory");
    }
    asm volatile("cp.async.commit_group;" ::: "memory");
  };

  fill(0,0); fill(1,1);

  for (int j = 0; j < kt; j++){
    asm volatile("cp.async.wait_group 1;" ::: "memory");
    __syncthreads();
    if (j+2 < kt) fill((j+2)%NSTG, j+2);
    else asm volatile("cp.async.commit_group;" ::: "memory");

    const uint32_t sb = smb + (uint32_t)(j%NSTG)*STAGE;
    #pragma unroll
    for (int ks = 0; ks < 2; ks++){
      uint32_t af[4][4], bf[NF][2];
      #pragma unroll
      for (int mt = 0; mt < 4; mt++)
        ldsm4(af[mt][0], af[mt][1], af[mt][2], af[mt][3], sb + offA[mt] + ks*32);
      #pragma unroll
      for (int np = 0; np < NPB; np++)
        ldsm4(bf[2*np][0], bf[2*np][1], bf[2*np+1][0], bf[2*np+1][1], sb + offB[np] + ks*32);
      #pragma unroll
      for (int mt = 0; mt < 4; mt++)
        #pragma unroll
        for (int nt = 0; nt < NF; nt++)
          mma16(acc[mt][nt], af[mt], bf[nt]);
    }
  }

  if (EPI == EPI_ATTN){
    __syncthreads();
    #pragma unroll
    for (int mt = 0; mt < 4; mt++){
      float p0 = 0.f, p1 = 0.f;
      #pragma unroll
      for (int nt = 0; nt < NF; nt++){
        int c = wn + nt*8 + 2*tq;
        float b0 = sBias[c]   + sQ[c];
        float b1 = sBias[c+1] + sQ[c+1];
        float v0 = sVw[c], v1 = sVw[c+1];
        p0 += tanhf(acc[mt][nt][0]+b0)*v0 + tanhf(acc[mt][nt][1]+b1)*v1;
        p1 += tanhf(acc[mt][nt][2]+b0)*v0 + tanhf(acc[mt][nt][3]+b1)*v1;
      }
      p0 += __shfl_xor_sync(0xffffffffu, p0, 1);
      p0 += __shfl_xor_sync(0xffffffffu, p0, 2);
      p1 += __shfl_xor_sync(0xffffffffu, p1, 1);
      p1 += __shfl_xor_sync(0xffffffffu, p1, 2);
      if (tq == 0){
        atomicAdd(&srow[wm+mt*16+g  ], p0);
        atomicAdd(&srow[wm+mt*16+g+8], p1);
      }
    }
    __syncthreads();
    if (tid < BM) spart[(size_t)blockIdx.x*M + m0 + tid] = srow[tid];
  } else {
    #pragma unroll
    for (int mt = 0; mt < 4; mt++){
      #pragma unroll
      for (int nt = 0; nt < NF; nt++){
        size_t r = m0 + wm + mt*16 + g;
        int c = n0 + wn + nt*8 + 2*tq;
        float b0 = sBias[c - n0], b1 = sBias[c - n0 + 1];
        float2* p0 = (float2*)(C + r*N + c);
        float2* p1 = (float2*)(C + (r+8)*N + c);
        *p0 = make_float2(acc[mt][nt][0]+b0, acc[mt][nt][1]+b1);
        *p1 = make_float2(acc[mt][nt][2]+b0, acc[mt][nt][3]+b1);
      }
    }
  }
}

// ============ fp32-input GEMM (inline cvt); OCC = min CTAs/SM ============
template<int BN, int EPI, int OCC>
__global__ void __launch_bounds__(256,OCC) gemm16(
    const float* __restrict__ A, const float* __restrict__ B1, const float* __restrict__ B2,
    int Ksplit, float* __restrict__ C, int M, int N, int K, int kLen,
    const float* __restrict__ bias,
    const float* __restrict__ qv, const float* __restrict__ vw, float* __restrict__ spart)
{
  constexpr int BM = 128, BK = 16;
  constexpr int WN = BN/4, NF = WN/8, NPB = NF/2;
  constexpr int RSB = 48;
  constexpr int STAGE = (BM+BN)*RSB;
  constexpr int NLD = (BM+BN)*4/256;

  extern __shared__ char dsm[];
  __shared__ float sBias[BN];
  const uint32_t smb = smem_u32(dsm);
  const int tid = threadIdx.x, warp = tid>>5, lane = tid&31;
  const int g = lane>>2, tq = lane&3;
  const int wm = (warp&1)*64, wn = (warp>>1)*WN;
  const size_t m0 = (size_t)blockIdx.y*BM;
  const int n0 = blockIdx.x*BN;
  const int kOff = blockIdx.z*kLen;
  const int kt = kLen/BK;
  const int K2 = K - Ksplit;

  if (tid < BN) sBias[tid] = bias ? bias[n0+tid] : 0.f;

  uint32_t offA[4], offB[NPB];
  {
    int rA = (lane & 15), kcA = (lane >> 4) * 16;
    #pragma unroll
    for (int mt = 0; mt < 4; mt++) offA[mt] = (uint32_t)((wm + mt*16 + rA)*RSB + kcA);
    int rB = (lane & 7) + ((lane >= 16) ? 8 : 0), kcB = ((lane >> 3) & 1) * 16;
    #pragma unroll
    for (int np = 0; np < NPB; np++) offB[np] = (uint32_t)((BM + wn + np*16 + rB)*RSB + kcB);
  }

  float acc[4][NF][4];
  #pragma unroll
  for (int i=0;i<4;i++)
    #pragma unroll
    for (int j=0;j<NF;j++)
      #pragma unroll
      for (int k=0;k<4;k++) acc[i][j][k]=0.f;

  float4 v[NLD];
  int rown[NLD], quad[NLD];
  #pragma unroll
  for (int i = 0; i < NLD; i++){ int c = tid + i*256; rown[i] = c>>2; quad[i] = c&3; }

  auto ldg = [&](int t){
    const int k0 = kOff + t*BK;
    #pragma unroll
    for (int i = 0; i < NLD; i++){
      int kg = k0 + quad[i]*4;
      const float* src;
      if (rown[i] < BM) src = A + (m0 + rown[i])*(size_t)K + kg;
      else {
        int n = n0 + rown[i] - BM;
        if (kg < Ksplit) src = B1 + (size_t)n*Ksplit + kg;
        else             src = B2 + (size_t)n*K2 + (kg - Ksplit);
      }
      v[i] = *(const float4*)src;
    }
  };
  auto sts = [&](int s){
    const uint32_t base = smb + (uint32_t)s*STAGE;
    #pragma unroll
    for (int i = 0; i < NLD; i++){
      uint32_t lo = packh2(make_float2(v[i].x, v[i].y));
      uint32_t hi = packh2(make_float2(v[i].z, v[i].w));
      uint32_t dst = base + (uint32_t)(rown[i]*RSB + quad[i]*8);
      asm volatile("st.shared.v2.u32 [%0], {%1,%2};" :: "r"(dst), "r"(lo), "r"(hi) : "memory");
    }
  };

  ldg(0); sts(0);
  if (kt > 1) ldg(1);
  __syncthreads();

  for (int j = 0; j < kt; j++){
    const uint32_t sb = smb + (uint32_t)(j&1)*STAGE;
    uint32_t af[4][4], bf[NF][2];
    #pragma unroll
    for (int mt = 0; mt < 4; mt++)
      ldsm4(af[mt][0], af[mt][1], af[mt][2], af[mt][3], sb + offA[mt]);
    #pragma unroll
    for (int np = 0; np < NPB; np++)
      ldsm4(bf[2*np][0], bf[2*np][1], bf[2*np+1][0], bf[2*np+1][1], sb + offB[np]);
    #pragma unroll
    for (int mt = 0; mt < 4; mt++)
      #pragma unroll
      for (int nt = 0; nt < NF; nt++)
        mma16(acc[mt][nt], af[mt], bf[nt]);
    if (j+1 < kt){
      sts((j+1)&1);
      if (j+2 < kt) ldg(j+2);
    }
    __syncthreads();
  }

  float* Cz = C + (size_t)blockIdx.z*M*N;
  #pragma unroll
  for (int mt = 0; mt < 4; mt++){
    #pragma unroll
    for (int nt = 0; nt < NF; nt++){
      size_t r = m0 + wm + mt*16 + g;
      int c = n0 + wn + nt*8 + 2*tq;
      float b0 = sBias[c - n0], b1 = sBias[c - n0 + 1];
      float2* p0 = (float2*)(Cz + r*N + c);
      float2* p1 = (float2*)(Cz + (r+8)*N + c);
      *p0 = make_float2(acc[mt][nt][0]+b0, acc[mt][nt][1]+b1);
      *p1 = make_float2(acc[mt][nt][2]+b0, acc[mt][nt][3]+b1);
    }
  }
}

// ================= small kernels =================
__global__ void conv_k(const float4* __restrict__ src, uint2* __restrict__ dst, int n4){
  int i = blockIdx.x*256 + threadIdx.x;
  if (i >= n4) return;
  float4 v = src[i];
  uint2 o;
  o.x = packh2(make_float2(v.x, v.y));
  o.y = packh2(make_float2(v.z, v.w));
  dst[i] = o;
}

__global__ void reduce_q_k(const float* __restrict__ qp, const float* __restrict__ w2b,
                           float* __restrict__ q){
  int i = blockIdx.x*256 + threadIdx.x;
  float s = w2b[i & (NH-1)];
  #pragma unroll
  for (int p = 0; p < 8; p++) s += qp[(size_t)p*NB*NH + i];
  q[i] = s;
}

// sums 8 n-slab score partials (+V_b) then softmax over S
__global__ void __launch_bounds__(NS) softmax_fused_k(const float* __restrict__ spart,
                                                      const float* __restrict__ vb,
                                                      float* __restrict__ attn_out){
  __shared__ float red[8];
  const int b = blockIdx.x, tid = threadIdx.x;
  const int m = b*NS + tid;
  float v = vb[0];
  #pragma unroll
  for (int j = 0; j < 8; j++) v += spart[(size_t)j*(NB*NS) + m];

  float mx = v;
  #pragma unroll
  for (int o = 16; o > 0; o >>= 1) mx = fmaxf(mx, __shfl_xor_sync(0xffffffffu, mx, o));
  if ((tid&31)==0) red[tid>>5] = mx;
  __syncthreads();
  if (tid == 0){ float x = red[0]; for (int i=1;i<8;i++) x = fmaxf(x, red[i]); red[0] = x; }
  __syncthreads();
  const float bm = red[0];
  __syncthreads();
  float e = expf(v - bm), s = e;
  #pragma unroll
  for (int o = 16; o > 0; o >>= 1) s += __shfl_xor_sync(0xffffffffu, s, o);
  if ((tid&31)==0) red[tid>>5] = s;
  __syncthreads();
  if (tid == 0){ float x = 0.f; for (int i=0;i<8;i++) x += red[i]; red[0] = x; }
  __syncthreads();
  attn_out[m] = e / red[0];
}

// context from fp16 enc; scatters into ctx, x0 slot, cat2 slot
__global__ void __launch_bounds__(128) ctx_k(const float* __restrict__ attn,
                                             const __half* __restrict__ ench,
                                             float* __restrict__ ctx,
                                             float* __restrict__ x0,
                                             float* __restrict__ cat2){
  __shared__ float sa[NS];
  const int b = blockIdx.x, hc = blockIdx.y, tid = threadIdx.x;
  sa[tid]     = attn[b*NS + tid];
  sa[tid+128] = attn[b*NS + tid + 128];
  __syncthreads();
  const int h4 = hc*512 + tid*4;
  const __half* ep = ench + (size_t)b*NS*NH + h4;
  float4 acc = make_float4(0.f,0.f,0.f,0.f);
  #pragma unroll 4
  for (int s = 0; s < NS; s++){
    uint2 u = *(const uint2*)(ep + (size_t)s*NH);
    float2 f01 = __half22float2(*(__half2*)&u.x);
    float2 f23 = __half22float2(*(__half2*)&u.y);
    float a = sa[s];
    acc.x += a*f01.x; acc.y += a*f01.y; acc.z += a*f23.x; acc.w += a*f23.y;
  }
  *(float4*)(ctx + b*NH + h4) = acc;
  *(float4*)(x0 + (size_t)b*(NE+2*NH) + NE + h4) = acc;
  *(float4*)(cat2 + (size_t)b*2*NH + NH + h4) = acc;
}

__global__ void prep_k(const int* __restrict__ tok, const float* __restrict__ emb,
                       const float* __restrict__ hidden,
                       float* __restrict__ x0, float* __restrict__ x1){
  int i = blockIdx.x*256 + threadIdx.x;
  if (i < NB*NE){
    int b = i >> 9, j = i & 511;
    x0[(size_t)b*(NE+2*NH) + j] = emb[(size_t)tok[b]*NE + j];
  } else if (i < NB*(NE+NH)){
    int t = i - NB*NE; int b = t >> 10, j = t & 1023;
    x0[(size_t)b*(NE+2*NH) + NE + NH + j] = hidden[b*NH + j];
  } else {
    int t = i - NB*(NE+NH); int b = t >> 10, j = t & 1023;
    x1[(size_t)b*2*NH + NH + j] = hidden[(size_t)NB*NH + b*NH + j];
  }
}

// sums 8 split-K gate partials + biases, applies LSTM cell; writes h to 2 dests
__global__ void lstm_k(const float* __restrict__ gp, const float* __restrict__ bih,
                       const float* __restrict__ bhh, const float* __restrict__ cprev,
                       float* __restrict__ hout, float* __restrict__ cout,
                       float* __restrict__ hout2){
  int i = blockIdx.x*256 + threadIdx.x;
  int b = i >> 10, h = i & 1023;
  const size_t base = (size_t)b*4*NH;
  float ig = bih[h]      + bhh[h];
  float fg = bih[NH+h]   + bhh[NH+h];
  float gg = bih[2*NH+h] + bhh[2*NH+h];
  float og = bih[3*NH+h] + bhh[3*NH+h];
  #pragma unroll
  for (int p = 0; p < 8; p++){
    const float* gr = gp + (size_t)p*NB*4*NH + base;
    ig += gr[h]; fg += gr[NH+h]; gg += gr[2*NH+h]; og += gr[3*NH+h];
  }
  float si = 1.f/(1.f+expf(-ig));
  float sf = 1.f/(1.f+expf(-fg));
  float so = 1.f/(1.f+expf(-og));
  float cn = sf*cprev[i] + si*tanhf(gg);
  float hv = so*tanhf(cn);
  cout[i] = cn;
  hout[i] = hv;
  hout2[(size_t)b*2*NH + h] = hv;
}

// log_softmax over 2 fc split-K partials (+bias)
__global__ void __launch_bounds__(1024) logsoftmax2_k(const float* __restrict__ fp,
                                                      const float* __restrict__ fcb,
                                                      float* __restrict__ pred){
  __shared__ float red[32];
  const int b = blockIdx.x, tid = threadIdx.x;
  const float* r0 = fp + (size_t)b*NV;
  const float* r1 = fp + (size_t)NB*NV + (size_t)b*NV;
  float* row = pred + (size_t)b*NV;

  float m = -1e30f;
  for (int i = tid; i < NV; i += 1024){
    float v = r0[i] + r1[i] + fcb[i];
    row[i] = v;
    m = fmaxf(m, v);
  }
  #pragma unroll
  for (int o = 16; o > 0; o >>= 1) m = fmaxf(m, __shfl_xor_sync(0xffffffffu, m, o));
  if ((tid&31)==0) red[tid>>5] = m;
  __syncthreads();
  if (tid < 32){
    float x = red[tid];
    #pragma unroll
    for (int o = 16; o > 0; o >>= 1) x = fmaxf(x, __shfl_xor_sync(0xffffffffu, x, o));
    if (tid == 0) red[0] = x;
  }
  __syncthreads();
  const float bm = red[0];
  __syncthreads();
  float s = 0.f;
  for (int i = tid; i < NV; i += 1024) s += expf(row[i] - bm);
  #pragma unroll
  for (int o = 16; o > 0; o >>= 1) s += __shfl_xor_sync(0xffffffffu, s, o);
  if ((tid&31)==0) red[tid>>5] = s;
  __syncthreads();
  if (tid < 32){
    float x = red[tid];
    #pragma unroll
    for (int o = 16; o > 0; o >>= 1) x += __shfl_xor_sync(0xffffffffu, x, o);
    if (tid == 0) red[0] = x;
  }
  __syncthreads();
  const float lg = bm + logf(red[0]);
  for (int i = tid; i < NV; i += 1024) row[i] = row[i] - lg;
}

// ================= launcher =================
extern "C" void kernel_launch(void* const* d_in, const int* in_sizes, int n_in,
                              void* d_out, int out_size){
  const int*   tok   = (const int*)  d_in[0];
  const float* hidden= (const float*)d_in[1];
  const float* cell  = (const float*)d_in[2];
  const float* enc   = (const float*)d_in[3];
  const float* emb   = (const float*)d_in[4];
  const float* W1w   = (const float*)d_in[5];
  const float* W1b   = (const float*)d_in[6];
  const float* W2w   = (const float*)d_in[7];
  const float* W2b   = (const float*)d_in[8];
  const float* Vw    = (const float*)d_in[9];
  const float* Vb    = (const float*)d_in[10];
  const float* wih0  = (const float*)d_in[11];
  const float* whh0  = (const float*)d_in[12];
  const float* bih0  = (const float*)d_in[13];
  const float* bhh0  = (const float*)d_in[14];
  const float* wih1  = (const float*)d_in[15];
  const float* whh1  = (const float*)d_in[16];
  const float* bih1  = (const float*)d_in[17];
  const float* bhh1  = (const float*)d_in[18];
  const float* fcw   = (const float*)d_in[19];
  const float* fcb   = (const float*)d_in[20];

  float* out    = (float*)d_out;
  float* pred   = out + OFF_PRED;
  float* hid_o  = out + OFF_HID;
  float* cell_o = out + OFF_CELL;
  float* attn_o = out + OFF_ATTN;

  __half *ench, *w1h;
  float *q, *qp, *spart, *ctx, *x0, *x1, *gp, *cat2, *fcp;
  cudaGetSymbolAddress((void**)&ench,   g_ench);
  cudaGetSymbolAddress((void**)&w1h,    g_w1h);
  cudaGetSymbolAddress((void**)&q,      g_q);
  cudaGetSymbolAddress((void**)&qp,     g_qpart);
  cudaGetSymbolAddress((void**)&spart,  g_spart);
  cudaGetSymbolAddress((void**)&ctx,    g_context);
  cudaGetSymbolAddress((void**)&x0,     g_x0);
  cudaGetSymbolAddress((void**)&x1,     g_x1);
  cudaGetSymbolAddress((void**)&gp,     g_gpart);
  cudaGetSymbolAddress((void**)&cat2,   g_cat2);
  cudaGetSymbolAddress((void**)&fcp,    g_fcpart);

  const int smHN = (128+128)*80*3;       // 61440 B (fp16-native, BN=128, occ 2)
  const int smC128 = (128+128)*48*2;     // 24576 B (inline, BN=128, occ 2)
  cudaFuncSetAttribute(gemm16h<128,EPI_ATTN>,   cudaFuncAttributeMaxDynamicSharedMemorySize, smHN);
  cudaFuncSetAttribute((const void*)gemm16<128,EPI_STORE,2>, cudaFuncAttributeMaxDynamicSharedMemorySize, smC128);

  // 0) fp16 pre-conversion: enc + W1
  conv_k<<<(NB*NS*NH/4)/256, 256>>>((const float4*)enc, (uint2*)ench, NB*NS*NH/4);
  conv_k<<<(NH*NH/4)/256, 256>>>((const float4*)W1w, (uint2*)w1h, NH*NH/4);

  // 0b) prep x0/x1 static parts
  prep_k<<<(NB*(NE+2*NH))/256, 256>>>(tok, emb, hidden, x0, x1);

  // 1) q partials: h_top @ W2^T (split-K 8, occ 2)
  gemm16<128,EPI_STORE,2><<<dim3(NH/128,1,8), 256, smC128>>>(
      hidden + (size_t)NB*NH, W2w, W2w, NH, qp, NB, NH, NH, NH/8,
      nullptr, nullptr, nullptr, nullptr);
  reduce_q_k<<<(NB*NH)/256, 256>>>(qp, W2b, q);

  // 2) fused energy + score partials (fp16-native, BN=128, 2 CTAs/SM)
  gemm16h<128,EPI_ATTN><<<dim3(NH/128, (NB*NS)/128), 256, smHN>>>(
      ench, w1h, nullptr, NB*NS, NH, NH, W1b, q, Vw, spart);

  // 3) score reduce (8 slabs) + softmax
  softmax_fused_k<<<NB, NS>>>(spart, Vb, attn_o);

  // 4) context (fp16 enc; scatters to x0, cat2)
  ctx_k<<<dim3(NB, NH/512), 128>>>(attn_o, ench, ctx, x0, cat2);

  // 5) gates0 partials: x0 @ [wih0|whh0]^T (split-K 8, occ 2)
  gemm16<128,EPI_STORE,2><<<dim3(4*NH/128,1,8), 256, smC128>>>(
      x0, wih0, whh0, NE+NH, gp, NB, 4*NH, NE+2*NH, (NE+2*NH)/8,
      nullptr, nullptr, nullptr, nullptr);

  // 6) LSTM cell 0
  lstm_k<<<(NB*NH)/256, 256>>>(gp, bih0, bhh0, cell, hid_o, cell_o, x1);

  // 7) gates1 partials: x1 @ [wih1|whh1]^T (split-K 8, occ 2)
  gemm16<128,EPI_STORE,2><<<dim3(4*NH/128,1,8), 256, smC128>>>(
      x1, wih1, whh1, NH, gp, NB, 4*NH, 2*NH, (2*NH)/8,
      nullptr, nullptr, nullptr, nullptr);

  // 8) LSTM cell 1
  lstm_k<<<(NB*NH)/256, 256>>>(gp, bih1, bhh1, cell + (size_t)NB*NH,
                               hid_o + (size_t)NB*NH, cell_o + (size_t)NB*NH, cat2);

  // 9) fc partials: cat2 @ fc_w^T (BN=128, split-K 2, occ 2 -> 500 CTAs)
  gemm16<128,EPI_STORE,2><<<dim3(NV/128,1,2), 256, smC128>>>(
      cat2, fcw, fcw, 2*NH, fcp, NB, NV, 2*NH, NH,
      nullptr, nullptr, nullptr, nullptr);

  // 10) 2-partial sum + bias + log_softmax
  logsoftmax2_k<<<NB, 1024>>>(fcp, fcb, pred);
}

// round 17
// speedup vs baseline: 1.2045x; 1.0217x over previous
#include <cuda_runtime.h>
#include <cstdint>
#include <cuda_fp16.h>

#define NB 128
#define NS 256
#define NH 1024
#define NE 512
#define NV 32000
#define NL 2

#define OFF_PRED 0
#define OFF_HID  (NB*NV)
#define OFF_CELL (OFF_HID + NL*NB*NH)
#define OFF_ATTN (OFF_CELL + NL*NB*NH)

#define EPI_STORE 0
#define EPI_ATTN  2

// -------- device scratch --------
__device__ __align__(16) __half g_ench[NB*NS*NH];    // fp16 encoder (67MB)
__device__ __align__(16) __half g_w1h[NH*NH];        // fp16 W1
__device__ __align__(16) float g_q[NB*NH];
__device__ __align__(16) float g_qpart[8*NB*NH];
__device__ __align__(16) float g_spart[8*NB*NS];     // 8 n-slabs
__device__ __align__(16) float g_context[NB*NH];
__device__ __align__(16) float g_x0[NB*(NE+2*NH)];   // [emb, ctx, h0_prev]
__device__ __align__(16) float g_x1[NB*2*NH];        // [h0_new, h1_prev]
__device__ __align__(16) float g_gpart[8*NB*4*NH];
__device__ __align__(16) float g_cat2[NB*2*NH];      // [h1_new, ctx]

__device__ __forceinline__ uint32_t smem_u32(const void* p){
  uint32_t a; asm("{ .reg .u64 t; cvta.to.shared.u64 t, %1; cvt.u32.u64 %0, t; }" : "=r"(a) : "l"(p));
  return a;
}
__device__ __forceinline__ uint32_t packh2(float2 v){
  uint32_t r; asm("cvt.rn.f16x2.f32 %0, %1, %2;" : "=r"(r) : "f"(v.y), "f"(v.x)); return r;
}
__device__ __forceinline__ void mma16(float* d, const uint32_t* a, const uint32_t* b){
  asm volatile("mma.sync.aligned.m16n8k16.row.col.f32.f16.f16.f32 "
    "{%0,%1,%2,%3},{%4,%5,%6,%7},{%8,%9},{%0,%1,%2,%3};"
    : "+f"(d[0]),"+f"(d[1]),"+f"(d[2]),"+f"(d[3])
    : "r"(a[0]),"r"(a[1]),"r"(a[2]),"r"(a[3]),"r"(b[0]),"r"(b[1]));
}
__device__ __forceinline__ void ldsm4(uint32_t& r0,uint32_t& r1,uint32_t& r2,uint32_t& r3, uint32_t addr){
  asm volatile("ldmatrix.sync.aligned.m8n8.x4.shared.b16 {%0,%1,%2,%3}, [%4];"
    : "=r"(r0),"=r"(r1),"=r"(r2),"=r"(r3) : "r"(addr));
}

// ============ fp16-NATIVE GEMM (attention): C(M,N)=A(M,K)@B(N,K)^T ============
// BN=128, 256 threads / 8 warps, 2 CTAs/SM. cp.async direct, BK=32, 3 stages.
template<int BN, int EPI>
__global__ void __launch_bounds__(256,2) gemm16h(
    const __half* __restrict__ A, const __half* __restrict__ B,
    float* __restrict__ C, int M, int N, int K,
    const float* __restrict__ bias,
    const float* __restrict__ qv, const float* __restrict__ vw, float* __restrict__ spart)
{
  constexpr int BM = 128, BK = 32, NSTG = 3;
  constexpr int WN = BN/4, NF = WN/8, NPB = NF/2;
  constexpr int RSB = 80;
  constexpr int STAGE = (BM+BN)*RSB;
  constexpr int CPT = (BM+BN)*4/256;

  extern __shared__ char dsm[];
  __shared__ float sBias[BN], sQ[BN], sVw[BN];
  __shared__ float srow[BM];

  const uint32_t smb = smem_u32(dsm);
  const int tid = threadIdx.x, warp = tid>>5, lane = tid&31;
  const int g = lane>>2, tq = lane&3;
  const int wm = (warp&1)*64, wn = (warp>>1)*WN;
  const size_t m0 = (size_t)blockIdx.y*BM;
  const int n0 = blockIdx.x*BN;
  const int kt = K/BK;

  if (tid < BN){
    sBias[tid] = bias ? bias[n0+tid] : 0.f;
    if (EPI == EPI_ATTN){ sVw[tid] = vw[n0+tid]; sQ[tid] = qv[(m0/NS)*NH + n0 + tid]; }
  }
  if (EPI == EPI_ATTN && tid < BM) srow[tid] = 0.f;

  uint32_t offA[4], offB[NPB];
  {
    int rA = (lane & 15), kcA = (lane >> 4) * 16;
    #pragma unroll
    for (int mt = 0; mt < 4; mt++) offA[mt] = (uint32_t)((wm + mt*16 + rA)*RSB + kcA);
    int rB = (lane & 7) + ((lane >= 16) ? 8 : 0), kcB = ((lane >> 3) & 1) * 16;
    #pragma unroll
    for (int np = 0; np < NPB; np++) offB[np] = (uint32_t)((BM + wn + np*16 + rB)*RSB + kcB);
  }

  float acc[4][NF][4];
  #pragma unroll
  for (int i=0;i<4;i++)
    #pragma unroll
    for (int j=0;j<NF;j++)
      #pragma unroll
      for (int k=0;k<4;k++) acc[i][j][k]=0.f;

  auto fill = [&](int s, int t){
    const uint32_t base = smb + (uint32_t)s*STAGE;
    const int k0 = t*BK;
    #pragma unroll
    for (int i = 0; i < CPT; i++){
      int c = tid + i*256;
      int row = c>>2, q = c&3;
      const __half* src = (row < BM)
        ? A + (m0 + row)*(size_t)K + k0 + q*8
        : B + (size_t)(n0 + row - BM)*K + k0 + q*8;
      uint32_t dst = base + (uint32_t)(row*RSB + q*16);
      asm volatile("cp.async.cg.shared.global [%0], [%1], 16;" :: "r"(dst), "l"(src) : "memory");
    }
    asm volatile("cp.async.commit_group;" ::: "memory");
  };

  fill(0,0); fill(1,1);

  for (int j = 0; j < kt; j++){
    asm volatile("cp.async.wait_group 1;" ::: "memory");
    __syncthreads();
    if (j+2 < kt) fill((j+2)%NSTG, j+2);
    else asm volatile("cp.async.commit_group;" ::: "memory");

    const uint32_t sb = smb + (uint32_t)(j%NSTG)*STAGE;
    #pragma unroll
    for (int ks = 0; ks < 2; ks++){
      uint32_t af[4][4], bf[NF][2];
      #pragma unroll
      for (int mt = 0; mt < 4; mt++)
        ldsm4(af[mt][0], af[mt][1], af[mt][2], af[mt][3], sb + offA[mt] + ks*32);
      #pragma unroll
      for (int np = 0; np < NPB; np++)
        ldsm4(bf[2*np][0], bf[2*np][1], bf[2*np+1][0], bf[2*np+1][1], sb + offB[np] + ks*32);
      #pragma unroll
      for (int mt = 0; mt < 4; mt++)
        #pragma unroll
        for (int nt = 0; nt < NF; nt++)
          mma16(acc[mt][nt], af[mt], bf[nt]);
    }
  }

  if (EPI == EPI_ATTN){
    __syncthreads();
    #pragma unroll
    for (int mt = 0; mt < 4; mt++){
      float p0 = 0.f, p1 = 0.f;
      #pragma unroll
      for (int nt = 0; nt < NF; nt++){
        int c = wn + nt*8 + 2*tq;
        float b0 = sBias[c]   + sQ[c];
        float b1 = sBias[c+1] + sQ[c+1];
        float v0 = sVw[c], v1 = sVw[c+1];
        p0 += tanhf(acc[mt][nt][0]+b0)*v0 + tanhf(acc[mt][nt][1]+b1)*v1;
        p1 += tanhf(acc[mt][nt][2]+b0)*v0 + tanhf(acc[mt][nt][3]+b1)*v1;
      }
      p0 += __shfl_xor_sync(0xffffffffu, p0, 1);
      p0 += __shfl_xor_sync(0xffffffffu, p0, 2);
      p1 += __shfl_xor_sync(0xffffffffu, p1, 1);
      p1 += __shfl_xor_sync(0xffffffffu, p1, 2);
      if (tq == 0){
        atomicAdd(&srow[wm+mt*16+g  ], p0);
        atomicAdd(&srow[wm+mt*16+g+8], p1);
      }
    }
    __syncthreads();
    if (tid < BM) spart[(size_t)blockIdx.x*M + m0 + tid] = srow[tid];
  } else {
    #pragma unroll
    for (int mt = 0; mt < 4; mt++){
      #pragma unroll
      for (int nt = 0; nt < NF; nt++){
        size_t r = m0 + wm + mt*16 + g;
        int c = n0 + wn + nt*8 + 2*tq;
        float b0 = sBias[c - n0], b1 = sBias[c - n0 + 1];
        float2* p0 = (float2*)(C + r*N + c);
        float2* p1 = (float2*)(C + (r+8)*N + c);
        *p0 = make_float2(acc[mt][nt][0]+b0, acc[mt][nt][1]+b1);
        *p1 = make_float2(acc[mt][nt][2]+b0, acc[mt][nt][3]+b1);
      }
    }
  }
}

// ============ fp32-input GEMM (inline cvt); OCC = min CTAs/SM ============
template<int BN, int EPI, int OCC>
__global__ void __launch_bounds__(256,OCC) gemm16(
    const float* __restrict__ A, const float* __restrict__ B1, const float* __restrict__ B2,
    int Ksplit, float* __restrict__ C, int M, int N, int K, int kLen,
    const float* __restrict__ bias,
    const float* __restrict__ qv, const float* __restrict__ vw, float* __restrict__ spart)
{
  constexpr int BM = 128, BK = 16;
  constexpr int WN = BN/4, NF = WN/8, NPB = NF/2;
  constexpr int RSB = 48;
  constexpr int STAGE = (BM+BN)*RSB;
  constexpr int NLD = (BM+BN)*4/256;

  extern __shared__ char dsm[];
  __shared__ float sBias[BN];
  const uint32_t smb = smem_u32(dsm);
  const int tid = threadIdx.x, warp = tid>>5, lane = tid&31;
  const int g = lane>>2, tq = lane&3;
  const int wm = (warp&1)*64, wn = (warp>>1)*WN;
  const size_t m0 = (size_t)blockIdx.y*BM;
  const int n0 = blockIdx.x*BN;
  const int kOff = blockIdx.z*kLen;
  const int kt = kLen/BK;
  const int K2 = K - Ksplit;

  if (tid < BN) sBias[tid] = bias ? bias[n0+tid] : 0.f;

  uint32_t offA[4], offB[NPB];
  {
    int rA = (lane & 15), kcA = (lane >> 4) * 16;
    #pragma unroll
    for (int mt = 0; mt < 4; mt++) offA[mt] = (uint32_t)((wm + mt*16 + rA)*RSB + kcA);
    int rB = (lane & 7) + ((lane >= 16) ? 8 : 0), kcB = ((lane >> 3) & 1) * 16;
    #pragma unroll
    for (int np = 0; np < NPB; np++) offB[np] = (uint32_t)((BM + wn + np*16 + rB)*RSB + kcB);
  }

  float acc[4][NF][4];
  #pragma unroll
  for (int i=0;i<4;i++)
    #pragma unroll
    for (int j=0;j<NF;j++)
      #pragma unroll
      for (int k=0;k<4;k++) acc[i][j][k]=0.f;

  float4 v[NLD];
  int rown[NLD], quad[NLD];
  #pragma unroll
  for (int i = 0; i < NLD; i++){ int c = tid + i*256; rown[i] = c>>2; quad[i] = c&3; }

  auto ldg = [&](int t){
    const int k0 = kOff + t*BK;
    #pragma unroll
    for (int i = 0; i < NLD; i++){
      int kg = k0 + quad[i]*4;
      const float* src;
      if (rown[i] < BM) src = A + (m0 + rown[i])*(size_t)K + kg;
      else {
        int n = n0 + rown[i] - BM;
        if (kg < Ksplit) src = B1 + (size_t)n*Ksplit + kg;
        else             src = B2 + (size_t)n*K2 + (kg - Ksplit);
      }
      v[i] = *(const float4*)src;
    }
  };
  auto sts = [&](int s){
    const uint32_t base = smb + (uint32_t)s*STAGE;
    #pragma unroll
    for (int i = 0; i < NLD; i++){
      uint32_t lo = packh2(make_float2(v[i].x, v[i].y));
      uint32_t hi = packh2(make_float2(v[i].z, v[i].w));
      uint32_t dst = base + (uint32_t)(rown[i]*RSB + quad[i]*8);
      asm volatile("st.shared.v2.u32 [%0], {%1,%2};" :: "r"(dst), "r"(lo), "r"(hi) : "memory");
    }
  };

  ldg(0); sts(0);
  if (kt > 1) ldg(1);
  __syncthreads();

  for (int j = 0; j < kt; j++){
    const uint32_t sb = smb + (uint32_t)(j&1)*STAGE;
    uint32_t af[4][4], bf[NF][2];
    #pragma unroll
    for (int mt = 0; mt < 4; mt++)
      ldsm4(af[mt][0], af[mt][1], af[mt][2], af[mt][3], sb + offA[mt]);
    #pragma unroll
    for (int np = 0; np < NPB; np++)
      ldsm4(bf[2*np][0], bf[2*np][1], bf[2*np+1][0], bf[2*np+1][1], sb + offB[np]);
    #pragma unroll
    for (int mt = 0; mt < 4; mt++)
      #pragma unroll
      for (int nt = 0; nt < NF; nt++)
        mma16(acc[mt][nt], af[mt], bf[nt]);
    if (j+1 < kt){
      sts((j+1)&1);
      if (j+2 < kt) ldg(j+2);
    }
    __syncthreads();
  }

  float* Cz = C + (size_t)blockIdx.z*M*N;
  #pragma unroll
  for (int mt = 0; mt < 4; mt++){
    #pragma unroll
    for (int nt = 0; nt < NF; nt++){
      size_t r = m0 + wm + mt*16 + g;
      int c = n0 + wn + nt*8 + 2*tq;
      float b0 = sBias[c - n0], b1 = sBias[c - n0 + 1];
      float2* p0 = (float2*)(Cz + r*N + c);
      float2* p1 = (float2*)(Cz + (r+8)*N + c);
      *p0 = make_float2(acc[mt][nt][0]+b0, acc[mt][nt][1]+b1);
      *p1 = make_float2(acc[mt][nt][2]+b0, acc[mt][nt][3]+b1);
    }
  }
}

// ================= small kernels =================
__global__ void conv_k(const float4* __restrict__ src, uint2* __restrict__ dst, int n4){
  int i = blockIdx.x*256 + threadIdx.x;
  if (i >= n4) return;
  float4 v = src[i];
  uint2 o;
  o.x = packh2(make_float2(v.x, v.y));
  o.y = packh2(make_float2(v.z, v.w));
  dst[i] = o;
}

__global__ void reduce_q_k(const float* __restrict__ qp, const float* __restrict__ w2b,
                           float* __restrict__ q){
  int i = blockIdx.x*256 + threadIdx.x;
  float s = w2b[i & (NH-1)];
  #pragma unroll
  for (int p = 0; p < 8; p++) s += qp[(size_t)p*NB*NH + i];
  q[i] = s;
}

// sums 8 n-slab score partials (+V_b) then softmax over S
__global__ void __launch_bounds__(NS) softmax_fused_k(const float* __restrict__ spart,
                                                      const float* __restrict__ vb,
                                                      float* __restrict__ attn_out){
  __shared__ float red[8];
  const int b = blockIdx.x, tid = threadIdx.x;
  const int m = b*NS + tid;
  float v = vb[0];
  #pragma unroll
  for (int j = 0; j < 8; j++) v += spart[(size_t)j*(NB*NS) + m];

  float mx = v;
  #pragma unroll
  for (int o = 16; o > 0; o >>= 1) mx = fmaxf(mx, __shfl_xor_sync(0xffffffffu, mx, o));
  if ((tid&31)==0) red[tid>>5] = mx;
  __syncthreads();
  if (tid == 0){ float x = red[0]; for (int i=1;i<8;i++) x = fmaxf(x, red[i]); red[0] = x; }
  __syncthreads();
  const float bm = red[0];
  __syncthreads();
  float e = expf(v - bm), s = e;
  #pragma unroll
  for (int o = 16; o > 0; o >>= 1) s += __shfl_xor_sync(0xffffffffu, s, o);
  if ((tid&31)==0) red[tid>>5] = s;
  __syncthreads();
  if (tid == 0){ float x = 0.f; for (int i=0;i<8;i++) x += red[i]; red[0] = x; }
  __syncthreads();
  attn_out[m] = e / red[0];
}

// context from fp16 enc; scatters into ctx, x0 slot, cat2 slot
__global__ void __launch_bounds__(128) ctx_k(const float* __restrict__ attn,
                                             const __half* __restrict__ ench,
                                             float* __restrict__ ctx,
                                             float* __restrict__ x0,
                                             float* __restrict__ cat2){
  __shared__ float sa[NS];
  const int b = blockIdx.x, hc = blockIdx.y, tid = threadIdx.x;
  sa[tid]     = attn[b*NS + tid];
  sa[tid+128] = attn[b*NS + tid + 128];
  __syncthreads();
  const int h4 = hc*512 + tid*4;
  const __half* ep = ench + (size_t)b*NS*NH + h4;
  float4 acc = make_float4(0.f,0.f,0.f,0.f);
  #pragma unroll 4
  for (int s = 0; s < NS; s++){
    uint2 u = *(const uint2*)(ep + (size_t)s*NH);
    float2 f01 = __half22float2(*(__half2*)&u.x);
    float2 f23 = __half22float2(*(__half2*)&u.y);
    float a = sa[s];
    acc.x += a*f01.x; acc.y += a*f01.y; acc.z += a*f23.x; acc.w += a*f23.y;
  }
  *(float4*)(ctx + b*NH + h4) = acc;
  *(float4*)(x0 + (size_t)b*(NE+2*NH) + NE + h4) = acc;
  *(float4*)(cat2 + (size_t)b*2*NH + NH + h4) = acc;
}

__global__ void prep_k(const int* __restrict__ tok, const float* __restrict__ emb,
                       const float* __restrict__ hidden,
                       float* __restrict__ x0, float* __restrict__ x1){
  int i = blockIdx.x*256 + threadIdx.x;
  if (i < NB*NE){
    int b = i >> 9, j = i & 511;
    x0[(size_t)b*(NE+2*NH) + j] = emb[(size_t)tok[b]*NE + j];
  } else if (i < NB*(NE+NH)){
    int t = i - NB*NE; int b = t >> 10, j = t & 1023;
    x0[(size_t)b*(NE+2*NH) + NE + NH + j] = hidden[b*NH + j];
  } else {
    int t = i - NB*(NE+NH); int b = t >> 10, j = t & 1023;
    x1[(size_t)b*2*NH + NH + j] = hidden[(size_t)NB*NH + b*NH + j];
  }
}

// sums 8 split-K gate partials + biases, applies LSTM cell; writes h to 2 dests
__global__ void lstm_k(const float* __restrict__ gp, const float* __restrict__ bih,
                       const float* __restrict__ bhh, const float* __restrict__ cprev,
                       float* __restrict__ hout, float* __restrict__ cout,
                       float* __restrict__ hout2){
  int i = blockIdx.x*256 + threadIdx.x;
  int b = i >> 10, h = i & 1023;
  const size_t base = (size_t)b*4*NH;
  float ig = bih[h]      + bhh[h];
  float fg = bih[NH+h]   + bhh[NH+h];
  float gg = bih[2*NH+h] + bhh[2*NH+h];
  float og = bih[3*NH+h] + bhh[3*NH+h];
  #pragma unroll
  for (int p = 0; p < 8; p++){
    const float* gr = gp + (size_t)p*NB*4*NH + base;
    ig += gr[h]; fg += gr[NH+h]; gg += gr[2*NH+h]; og += gr[3*NH+h];
  }
  float si = 1.f/(1.f+expf(-ig));
  float sf = 1.f/(1.f+expf(-fg));
  float so = 1.f/(1.f+expf(-og));
  float cn = sf*cprev[i] + si*tanhf(gg);
  float hv = so*tanhf(cn);
  cout[i] = cn;
  hout[i] = hv;
  hout2[(size_t)b*2*NH + h] = hv;
}

// in-place log_softmax
__global__ void __launch_bounds__(1024) logsoftmax_k(float* __restrict__ pred){
  __shared__ float red[32];
  const int b = blockIdx.x, tid = threadIdx.x;
  float* row = pred + (size_t)b*NV;
  float m = -1e30f;
  for (int i = tid; i < NV; i += 1024) m = fmaxf(m, row[i]);
  #pragma unroll
  for (int o = 16; o > 0; o >>= 1) m = fmaxf(m, __shfl_xor_sync(0xffffffffu, m, o));
  if ((tid&31)==0) red[tid>>5] = m;
  __syncthreads();
  if (tid < 32){
    float x = red[tid];
    #pragma unroll
    for (int o = 16; o > 0; o >>= 1) x = fmaxf(x, __shfl_xor_sync(0xffffffffu, x, o));
    if (tid == 0) red[0] = x;
  }
  __syncthreads();
  const float bm = red[0];
  __syncthreads();
  float s = 0.f;
  for (int i = tid; i < NV; i += 1024) s += expf(row[i] - bm);
  #pragma unroll
  for (int o = 16; o > 0; o >>= 1) s += __shfl_xor_sync(0xffffffffu, s, o);
  if ((tid&31)==0) red[tid>>5] = s;
  __syncthreads();
  if (tid < 32){
    float x = red[tid];
    #pragma unroll
    for (int o = 16; o > 0; o >>= 1) x += __shfl_xor_sync(0xffffffffu, x, o);
    if (tid == 0) red[0] = x;
  }
  __syncthreads();
  const float lg = bm + logf(red[0]);
  for (int i = tid; i < NV; i += 1024) row[i] = row[i] - lg;
}

// ================= launcher =================
extern "C" void kernel_launch(void* const* d_in, const int* in_sizes, int n_in,
                              void* d_out, int out_size){
  const int*   tok   = (const int*)  d_in[0];
  const float* hidden= (const float*)d_in[1];
  const float* cell  = (const float*)d_in[2];
  const float* enc   = (const float*)d_in[3];
  const float* emb   = (const float*)d_in[4];
  const float* W1w   = (const float*)d_in[5];
  const float* W1b   = (const float*)d_in[6];
  const float* W2w   = (const float*)d_in[7];
  const float* W2b   = (const float*)d_in[8];
  const float* Vw    = (const float*)d_in[9];
  const float* Vb    = (const float*)d_in[10];
  const float* wih0  = (const float*)d_in[11];
  const float* whh0  = (const float*)d_in[12];
  const float* bih0  = (const float*)d_in[13];
  const float* bhh0  = (const float*)d_in[14];
  const float* wih1  = (const float*)d_in[15];
  const float* whh1  = (const float*)d_in[16];
  const float* bih1  = (const float*)d_in[17];
  const float* bhh1  = (const float*)d_in[18];
  const float* fcw   = (const float*)d_in[19];
  const float* fcb   = (const float*)d_in[20];

  float* out    = (float*)d_out;
  float* pred   = out + OFF_PRED;
  float* hid_o  = out + OFF_HID;
  float* cell_o = out + OFF_CELL;
  float* attn_o = out + OFF_ATTN;

  __half *ench, *w1h;
  float *q, *qp, *spart, *ctx, *x0, *x1, *gp, *cat2;
  cudaGetSymbolAddress((void**)&ench,   g_ench);
  cudaGetSymbolAddress((void**)&w1h,    g_w1h);
  cudaGetSymbolAddress((void**)&q,      g_q);
  cudaGetSymbolAddress((void**)&qp,     g_qpart);
  cudaGetSymbolAddress((void**)&spart,  g_spart);
  cudaGetSymbolAddress((void**)&ctx,    g_context);
  cudaGetSymbolAddress((void**)&x0,     g_x0);
  cudaGetSymbolAddress((void**)&x1,     g_x1);
  cudaGetSymbolAddress((void**)&gp,     g_gpart);
  cudaGetSymbolAddress((void**)&cat2,   g_cat2);

  const int smHN = (128+128)*80*3;       // 61440 B (fp16-native, BN=128, occ 2)
  const int smC128 = (128+128)*48*2;     // 24576 B (inline, BN=128, occ 2)
  cudaFuncSetAttribute(gemm16h<128,EPI_ATTN>,   cudaFuncAttributeMaxDynamicSharedMemorySize, smHN);
  cudaFuncSetAttribute((const void*)gemm16<128,EPI_STORE,2>, cudaFuncAttributeMaxDynamicSharedMemorySize, smC128);

  // 0) fp16 pre-conversion: enc + W1
  conv_k<<<(NB*NS*NH/4)/256, 256>>>((const float4*)enc, (uint2*)ench, NB*NS*NH/4);
  conv_k<<<(NH*NH/4)/256, 256>>>((const float4*)W1w, (uint2*)w1h, NH*NH/4);

  // 0b) prep x0/x1 static parts
  prep_k<<<(NB*(NE+2*NH))/256, 256>>>(tok, emb, hidden, x0, x1);

  // 1) q partials: h_top @ W2^T (split-K 8, occ 2)
  gemm16<128,EPI_STORE,2><<<dim3(NH/128,1,8), 256, smC128>>>(
      hidden + (size_t)NB*NH, W2w, W2w, NH, qp, NB, NH, NH, NH/8,
      nullptr, nullptr, nullptr, nullptr);
  reduce_q_k<<<(NB*NH)/256, 256>>>(qp, W2b, q);

  // 2) fused energy + score partials (fp16-native, BN=128, 2 CTAs/SM)
  gemm16h<128,EPI_ATTN><<<dim3(NH/128, (NB*NS)/128), 256, smHN>>>(
      ench, w1h, nullptr, NB*NS, NH, NH, W1b, q, Vw, spart);

  // 3) score reduce (8 slabs) + softmax
  softmax_fused_k<<<NB, NS>>>(spart, Vb, attn_o);

  // 4) context (fp16 enc; scatters to x0, cat2)
  ctx_k<<<dim3(NB, NH/512), 128>>>(attn_o, ench, ctx, x0, cat2);

  // 5) gates0 partials: x0 @ [wih0|whh0]^T (split-K 8, occ 2)
  gemm16<128,EPI_STORE,2><<<dim3(4*NH/128,1,8), 256, smC128>>>(
      x0, wih0, whh0, NE+NH, gp, NB, 4*NH, NE+2*NH, (NE+2*NH)/8,
      nullptr, nullptr, nullptr, nullptr);

  // 6) LSTM cell 0
  lstm_k<<<(NB*NH)/256, 256>>>(gp, bih0, bhh0, cell, hid_o, cell_o, x1);

  // 7) gates1 partials: x1 @ [wih1|whh1]^T (split-K 8, occ 2)
  gemm16<128,EPI_STORE,2><<<dim3(4*NH/128,1,8), 256, smC128>>>(
      x1, wih1, whh1, NH, gp, NB, 4*NH, 2*NH, (2*NH)/8,
      nullptr, nullptr, nullptr, nullptr);

  // 8) LSTM cell 1
  lstm_k<<<(NB*NH)/256, 256>>>(gp, bih1, bhh1, cell + (size_t)NB*NH,
                               hid_o + (size_t)NB*NH, cell_o + (size_t)NB*NH, cat2);

  // 9) logits = cat2 @ fc_w^T + fc_b  (no split-K: 250 CTAs, single wave @ occ 2)
  gemm16<128,EPI_STORE,2><<<dim3(NV/128,1,1), 256, smC128>>>(
      cat2, fcw, fcw, 2*NH, pred, NB, NV, 2*NH, 2*NH,
      fcb, nullptr, nullptr, nullptr);

  // 10) in-place log_softmax
  logsoftmax_k<<<NB, 1024>>>(pred);
}